// round 1
// baseline (speedup 1.0000x reference)
#include <cuda_runtime.h>
#include <cstdint>

#define DD   768
#define TT   1024
#define BBATCH 4
#define MM   4096          // B*T
#define HH   6
#define HSZ  128
#define FFD  3072
#define VV   32000
#define LL   6

// ---------------- scratch (device globals: allocation-free) ----------------
__device__ float g_x[MM * DD];                    // residual stream
__device__ float g_h[MM * DD];                    // layernorm output
__device__ float g_qkv[MM * 3 * DD];              // packed q|k|v
__device__ float g_att[MM * DD];                  // attention output (b,t,h*128+e)
__device__ float g_ff[MM * FFD];                  // ff hidden
__device__ float g_scores[(size_t)BBATCH * HH * TT * TT];  // attention scores
__device__ float g_wqkv[LL * DD * 3 * DD];        // repacked qkv weights

// ---------------- weight repack: wq/wk/wv [L,H,D,HS] -> [L][D][3D] ----------
__global__ void repack_qkv_k(const float* __restrict__ wq,
                             const float* __restrict__ wk,
                             const float* __restrict__ wv) {
    int i = blockIdx.x * blockDim.x + threadIdx.x;
    const int total = LL * HH * DD * HSZ;
    if (i >= total) return;
    int e = i % HSZ;
    int d = (i / HSZ) % DD;
    int h = (i / (HSZ * DD)) % HH;
    int l = i / (HSZ * DD * HH);
    float* out = g_wqkv + (size_t)(l * DD + d) * (3 * DD);
    int c = h * HSZ + e;
    out[c]          = wq[i];
    out[DD + c]     = wk[i];
    out[2 * DD + c] = wv[i];
}

// ---------------- embedding ----------------
__global__ void embed_k(const int* __restrict__ idx,
                        const float* __restrict__ tok,
                        const float* __restrict__ pos) {
    int i = blockIdx.x * blockDim.x + threadIdx.x;  // MM*DD
    if (i >= MM * DD) return;
    int d = i % DD;
    int m = i / DD;
    int t = m % TT;
    g_x[i] = tok[(size_t)idx[m] * DD + d] + pos[t * DD + d];
}

// ---------------- layernorm (block per row of 768) ----------------
__global__ void layernorm_k(const float* __restrict__ x,
                            const float* __restrict__ g,
                            const float* __restrict__ b,
                            float* __restrict__ out) {
    int row = blockIdx.x;
    const float* xr = x + (size_t)row * DD;
    int tid = threadIdx.x;  // 256
    float v0 = xr[tid], v1 = xr[tid + 256], v2 = xr[tid + 512];
    float s = v0 + v1 + v2;
    float sq = v0 * v0 + v1 * v1 + v2 * v2;
    __shared__ float shs[8], shq[8];
    #pragma unroll
    for (int o = 16; o; o >>= 1) {
        s  += __shfl_xor_sync(0xffffffffu, s, o);
        sq += __shfl_xor_sync(0xffffffffu, sq, o);
    }
    if ((tid & 31) == 0) { shs[tid >> 5] = s; shq[tid >> 5] = sq; }
    __syncthreads();
    if (tid < 32) {
        s  = (tid < 8) ? shs[tid] : 0.f;
        sq = (tid < 8) ? shq[tid] : 0.f;
        #pragma unroll
        for (int o = 4; o; o >>= 1) {
            s  += __shfl_xor_sync(0xffffffffu, s, o);
            sq += __shfl_xor_sync(0xffffffffu, sq, o);
        }
        if (tid == 0) { shs[0] = s; shq[0] = sq; }
    }
    __syncthreads();
    float mean = shs[0] * (1.f / DD);
    float var  = shq[0] * (1.f / DD) - mean * mean;
    float r = rsqrtf(var + 1e-5f);
    float* o = out + (size_t)row * DD;
    o[tid]       = (v0 - mean) * r * g[tid]       + b[tid];
    o[tid + 256] = (v1 - mean) * r * g[tid + 256] + b[tid + 256];
    o[tid + 512] = (v2 - mean) * r * g[tid + 512] + b[tid + 512];
}

// ---------------- generic SGEMM: C[M,N] = A[M,K] * B[K,N] (+epilogue) -------
// EPI: 0 none, 1 bias, 2 bias+relu, 3 bias+residual
template <int EPI>
__global__ void __launch_bounds__(256)
sgemm_k(int M, int N, int K,
        const float* __restrict__ A, const float* __restrict__ B,
        const float* __restrict__ bias, const float* __restrict__ res,
        float* __restrict__ C) {
    const int BM = 128, BN = 128, BK = 8, TM = 8, TN = 8;
    __shared__ float As[BK][BM];
    __shared__ float Bs[BK][BN];
    int cRow = blockIdx.y, cCol = blockIdx.x;
    A += (size_t)cRow * BM * K;
    B += (size_t)cCol * BN;
    size_t cOff = (size_t)cRow * BM * N + (size_t)cCol * BN;
    C += cOff;
    if (EPI == 3) res += cOff;
    int tid = threadIdx.x;
    int innerRowA = tid >> 1, innerColA = (tid & 1) * 4;
    int innerRowB = tid >> 5, innerColB = (tid & 31) * 4;
    int threadRow = tid >> 4, threadCol = tid & 15;

    float acc[TM][TN];
    #pragma unroll
    for (int i = 0; i < TM; i++)
        #pragma unroll
        for (int j = 0; j < TN; j++) acc[i][j] = 0.f;
    float regM[TM], regN[TN];

    for (int k0 = 0; k0 < K; k0 += BK) {
        float4 a = *(const float4*)(A + (size_t)innerRowA * K + innerColA);
        As[innerColA + 0][innerRowA] = a.x;
        As[innerColA + 1][innerRowA] = a.y;
        As[innerColA + 2][innerRowA] = a.z;
        As[innerColA + 3][innerRowA] = a.w;
        *(float4*)(&Bs[innerRowB][innerColB]) =
            *(const float4*)(B + (size_t)innerRowB * N + innerColB);
        __syncthreads();
        A += BK;
        B += (size_t)BK * N;
        #pragma unroll
        for (int k = 0; k < BK; k++) {
            #pragma unroll
            for (int i = 0; i < TM; i++) regM[i] = As[k][threadRow * TM + i];
            #pragma unroll
            for (int j = 0; j < TN; j++) regN[j] = Bs[k][threadCol * TN + j];
            #pragma unroll
            for (int i = 0; i < TM; i++)
                #pragma unroll
                for (int j = 0; j < TN; j++)
                    acc[i][j] += regM[i] * regN[j];
        }
        __syncthreads();
    }

    #pragma unroll
    for (int i = 0; i < TM; i++) {
        int r = threadRow * TM + i;
        #pragma unroll
        for (int j = 0; j < TN; j++) {
            int cc = threadCol * TN + j;
            float v = acc[i][j];
            if (EPI >= 1) v += bias[cCol * BN + cc];
            if (EPI == 2) v = fmaxf(v, 0.f);
            if (EPI == 3) v += res[(size_t)r * N + cc];
            C[(size_t)r * N + cc] = v;
        }
    }
}

// ---------------- attention scores: S = Q K^T * scale, causal masked --------
__global__ void __launch_bounds__(256)
attn_scores_k(void) {
    const int bh = blockIdx.z;
    const int b = bh / HH, h = bh % HH;
    const int tqb = blockIdx.y * 64, tsb = blockIdx.x * 64;
    float* Sout = g_scores + (size_t)bh * TT * TT;
    int tid = threadIdx.x;
    int tr = tid >> 4, tc = tid & 15;  // 16x16 threads, each 4x4

    if (tsb > tqb + 63) {
        #pragma unroll
        for (int i = 0; i < 4; i++)
            #pragma unroll
            for (int j = 0; j < 4; j++)
                Sout[(size_t)(tqb + tr * 4 + i) * TT + tsb + tc * 4 + j] = -1e30f;
        return;
    }

    __shared__ float Qs[16][64];
    __shared__ float Ks[16][64];
    const float* Qbase = g_qkv + (size_t)(b * TT + tqb) * (3 * DD) + h * HSZ;
    const float* Kbase = g_qkv + (size_t)(b * TT + tsb) * (3 * DD) + DD + h * HSZ;
    int lr = tid >> 2, lc = (tid & 3) * 4;  // 64 rows x 16 cols loads

    float acc[4][4];
    #pragma unroll
    for (int i = 0; i < 4; i++)
        #pragma unroll
        for (int j = 0; j < 4; j++) acc[i][j] = 0.f;

    for (int k0 = 0; k0 < HSZ; k0 += 16) {
        float4 q = *(const float4*)(Qbase + (size_t)lr * (3 * DD) + k0 + lc);
        Qs[lc + 0][lr] = q.x; Qs[lc + 1][lr] = q.y;
        Qs[lc + 2][lr] = q.z; Qs[lc + 3][lr] = q.w;
        float4 kk = *(const float4*)(Kbase + (size_t)lr * (3 * DD) + k0 + lc);
        Ks[lc + 0][lr] = kk.x; Ks[lc + 1][lr] = kk.y;
        Ks[lc + 2][lr] = kk.z; Ks[lc + 3][lr] = kk.w;
        __syncthreads();
        #pragma unroll
        for (int k = 0; k < 16; k++) {
            float rq[4], rk[4];
            #pragma unroll
            for (int i = 0; i < 4; i++) rq[i] = Qs[k][tr * 4 + i];
            #pragma unroll
            for (int j = 0; j < 4; j++) rk[j] = Ks[k][tc * 4 + j];
            #pragma unroll
            for (int i = 0; i < 4; i++)
                #pragma unroll
                for (int j = 0; j < 4; j++)
                    acc[i][j] += rq[i] * rk[j];
        }
        __syncthreads();
    }

    const float scale = 0.08838834764831845f;  // 128^-0.5
    #pragma unroll
    for (int i = 0; i < 4; i++) {
        int t = tqb + tr * 4 + i;
        #pragma unroll
        for (int j = 0; j < 4; j++) {
            int s = tsb + tc * 4 + j;
            Sout[(size_t)t * TT + s] = (s <= t) ? acc[i][j] * scale : -1e30f;
        }
    }
}

// ---------------- row softmax over 1024 ----------------
__global__ void softmax_k(void) {
    size_t row = blockIdx.x;
    float* p = g_scores + row * TT;
    int tid = threadIdx.x;
    float v[4];
    #pragma unroll
    for (int i = 0; i < 4; i++) v[i] = p[tid + i * 256];
    float mx = fmaxf(fmaxf(v[0], v[1]), fmaxf(v[2], v[3]));
    __shared__ float sh[8];
    __shared__ float bc;
    #pragma unroll
    for (int o = 16; o; o >>= 1) mx = fmaxf(mx, __shfl_xor_sync(0xffffffffu, mx, o));
    if ((tid & 31) == 0) sh[tid >> 5] = mx;
    __syncthreads();
    if (tid < 32) {
        mx = (tid < 8) ? sh[tid] : -1e30f;
        #pragma unroll
        for (int o = 4; o; o >>= 1) mx = fmaxf(mx, __shfl_xor_sync(0xffffffffu, mx, o));
        if (tid == 0) bc = mx;
    }
    __syncthreads();
    mx = bc;
    float sum = 0.f;
    #pragma unroll
    for (int i = 0; i < 4; i++) { v[i] = __expf(v[i] - mx); sum += v[i]; }
    __syncthreads();
    #pragma unroll
    for (int o = 16; o; o >>= 1) sum += __shfl_xor_sync(0xffffffffu, sum, o);
    if ((tid & 31) == 0) sh[tid >> 5] = sum;
    __syncthreads();
    if (tid < 32) {
        sum = (tid < 8) ? sh[tid] : 0.f;
        #pragma unroll
        for (int o = 4; o; o >>= 1) sum += __shfl_xor_sync(0xffffffffu, sum, o);
        if (tid == 0) bc = sum;
    }
    __syncthreads();
    float inv = 1.f / bc;
    #pragma unroll
    for (int i = 0; i < 4; i++) p[tid + i * 256] = v[i] * inv;
}

// ---------------- PV: att = P V (causally truncated K loop) ----------------
__global__ void __launch_bounds__(256)
attn_pv_k(void) {
    const int bh = blockIdx.z;
    const int b = bh / HH, h = bh % HH;
    const int tqb = blockIdx.y * 64, eb = blockIdx.x * 64;
    const float* P = g_scores + (size_t)bh * TT * TT + (size_t)tqb * TT;
    const float* V = g_qkv + (size_t)(b * TT) * (3 * DD) + 2 * DD + h * HSZ + eb;
    int tid = threadIdx.x;
    int tr = tid >> 4, tc = tid & 15;
    int lrP = tid >> 2, lcP = (tid & 3) * 4;   // P: 64 rows x 16 k
    int lrV = tid >> 4, lcV = (tid & 15) * 4;  // V: 16 k x 64 cols

    __shared__ float Ps[16][64];
    __shared__ float Vs[16][64];

    float acc[4][4];
    #pragma unroll
    for (int i = 0; i < 4; i++)
        #pragma unroll
        for (int j = 0; j < 4; j++) acc[i][j] = 0.f;

    int kmax = tqb + 64;  // probabilities beyond causal bound are exactly 0
    for (int k0 = 0; k0 < kmax; k0 += 16) {
        float4 pv = *(const float4*)(P + (size_t)lrP * TT + k0 + lcP);
        Ps[lcP + 0][lrP] = pv.x; Ps[lcP + 1][lrP] = pv.y;
        Ps[lcP + 2][lrP] = pv.z; Ps[lcP + 3][lrP] = pv.w;
        *(float4*)(&Vs[lrV][lcV]) =
            *(const float4*)(V + (size_t)(k0 + lrV) * (3 * DD) + lcV);
        __syncthreads();
        #pragma unroll
        for (int k = 0; k < 16; k++) {
            float rp[4], rv[4];
            #pragma unroll
            for (int i = 0; i < 4; i++) rp[i] = Ps[k][tr * 4 + i];
            #pragma unroll
            for (int j = 0; j < 4; j++) rv[j] = Vs[k][tc * 4 + j];
            #pragma unroll
            for (int i = 0; i < 4; i++)
                #pragma unroll
                for (int j = 0; j < 4; j++)
                    acc[i][j] += rp[i] * rv[j];
        }
        __syncthreads();
    }

    #pragma unroll
    for (int i = 0; i < 4; i++) {
        int t = tqb + tr * 4 + i;
        #pragma unroll
        for (int j = 0; j < 4; j++) {
            int e = eb + tc * 4 + j;
            g_att[(size_t)(b * TT + t) * DD + h * HSZ + e] = acc[i][j];
        }
    }
}

// ---------------- host orchestration ----------------
extern "C" void kernel_launch(void* const* d_in, const int* in_sizes, int n_in,
                              void* d_out, int out_size) {
    const int*   idx     = (const int*)d_in[0];
    const float* tok_emb = (const float*)d_in[1];
    const float* pos_emb = (const float*)d_in[2];
    const float* wq      = (const float*)d_in[3];
    const float* wk      = (const float*)d_in[4];
    const float* wv      = (const float*)d_in[5];
    const float* wo      = (const float*)d_in[6];
    const float* bo      = (const float*)d_in[7];
    const float* w1      = (const float*)d_in[8];
    const float* b1      = (const float*)d_in[9];
    const float* w2      = (const float*)d_in[10];
    const float* b2      = (const float*)d_in[11];
    const float* g1      = (const float*)d_in[12];
    const float* be1     = (const float*)d_in[13];
    const float* g2      = (const float*)d_in[14];
    const float* be2     = (const float*)d_in[15];
    const float* wlm     = (const float*)d_in[16];
    const float* blm     = (const float*)d_in[17];
    float* out = (float*)d_out;

    float *px, *ph, *pqkv, *patt, *pff, *pwqkv;
    cudaGetSymbolAddress((void**)&px,    g_x);
    cudaGetSymbolAddress((void**)&ph,    g_h);
    cudaGetSymbolAddress((void**)&pqkv,  g_qkv);
    cudaGetSymbolAddress((void**)&patt,  g_att);
    cudaGetSymbolAddress((void**)&pff,   g_ff);
    cudaGetSymbolAddress((void**)&pwqkv, g_wqkv);

    // weight repack + embedding
    {
        int total = LL * HH * DD * HSZ;
        repack_qkv_k<<<(total + 255) / 256, 256>>>(wq, wk, wv);
        embed_k<<<(MM * DD + 255) / 256, 256>>>(idx, tok_emb, pos_emb);
    }

    for (int l = 0; l < LL; l++) {
        // ln1
        layernorm_k<<<MM, 256>>>(px, g1 + l * DD, be1 + l * DD, ph);
        // qkv
        {
            dim3 grid(3 * DD / 128, MM / 128);
            sgemm_k<0><<<grid, 256>>>(MM, 3 * DD, DD, ph,
                                      pwqkv + (size_t)l * DD * 3 * DD,
                                      nullptr, nullptr, pqkv);
        }
        // attention
        attn_scores_k<<<dim3(16, 16, BBATCH * HH), 256>>>();
        softmax_k<<<BBATCH * HH * TT, 256>>>();
        attn_pv_k<<<dim3(2, 16, BBATCH * HH), 256>>>();
        // proj + bias + residual (in-place into x)
        {
            dim3 grid(DD / 128, MM / 128);
            sgemm_k<3><<<grid, 256>>>(MM, DD, DD, patt,
                                      wo + (size_t)l * DD * DD,
                                      bo + l * DD, px, px);
        }
        // ln2
        layernorm_k<<<MM, 256>>>(px, g2 + l * DD, be2 + l * DD, ph);
        // ff1 (bias + relu)
        {
            dim3 grid(FFD / 128, MM / 128);
            sgemm_k<2><<<grid, 256>>>(MM, FFD, DD, ph,
                                      w1 + (size_t)l * DD * FFD,
                                      b1 + l * FFD, nullptr, pff);
        }
        // ff2 (bias + residual into x)
        {
            dim3 grid(DD / 128, MM / 128);
            sgemm_k<3><<<grid, 256>>>(MM, DD, FFD, pff,
                                      w2 + (size_t)l * FFD * DD,
                                      b2 + l * DD, px, px);
        }
    }

    // LM head: out = x @ wlm + blm
    {
        dim3 grid(VV / 128, MM / 128);
        sgemm_k<1><<<grid, 256>>>(MM, VV, DD, px, wlm, blm, nullptr, out);
    }
}

// round 3
// speedup vs baseline: 1.1937x; 1.1937x over previous
#include <cuda_runtime.h>
#include <cstdint>

#define DD   768
#define TT   1024
#define BBATCH 4
#define MM   4096          // B*T
#define HH   6
#define HSZ  128
#define FFD  3072
#define VV   32000
#define LL   6

// ======================= tf32 helpers =======================
static __device__ __forceinline__ float2 tf32split(float a) {
    uint32_t hu;
    asm("cvt.rna.tf32.f32 %0, %1;" : "=r"(hu) : "f"(a));
    float hi = __uint_as_float(hu);
    float r = a - hi;
    uint32_t lu;
    asm("cvt.rna.tf32.f32 %0, %1;" : "=r"(lu) : "f"(r));
    return make_float2(hi, __uint_as_float(lu));
}

static __device__ __forceinline__ void mma_tf32(float* d, const uint32_t* a,
                                                const uint32_t* b) {
    asm volatile(
        "mma.sync.aligned.m16n8k8.row.col.f32.tf32.tf32.f32 "
        "{%0,%1,%2,%3}, {%4,%5,%6,%7}, {%8,%9}, {%0,%1,%2,%3};"
        : "+f"(d[0]), "+f"(d[1]), "+f"(d[2]), "+f"(d[3])
        : "r"(a[0]), "r"(a[1]), "r"(a[2]), "r"(a[3]), "r"(b[0]), "r"(b[1]));
}

static __device__ __forceinline__ void cp_async16(uint32_t dst_smem, const void* src) {
    asm volatile("cp.async.ca.shared.global [%0], [%1], 16;"
                 :: "r"(dst_smem), "l"(src) : "memory");
}
static __device__ __forceinline__ uint32_t smem_u32(const void* p) {
    uint32_t a;
    asm("{ .reg .u64 t; cvta.to.shared.u64 t, %1; cvt.u32.u64 %0, t; }"
        : "=r"(a) : "l"(p));
    return a;
}

// ======================= scratch (device globals) =======================
__device__ float g_x[MM * DD];
__device__ float g_h[MM * DD];
__device__ float g_qkv[MM * 3 * DD];
__device__ float g_att[MM * DD];
__device__ float g_ff[MM * FFD];
__device__ float g_scores[(size_t)BBATCH * HH * TT * TT];

// split+transposed weights (B^T layout: [N][K], tf32 hi/lo)
__device__ float g_wqkvT_hi[LL * 3 * DD * DD];
__device__ float g_wqkvT_lo[LL * 3 * DD * DD];
__device__ float g_woT_hi[LL * DD * DD];
__device__ float g_woT_lo[LL * DD * DD];
__device__ float g_w1T_hi[LL * FFD * DD];
__device__ float g_w1T_lo[LL * FFD * DD];
__device__ float g_w2T_hi[LL * DD * FFD];
__device__ float g_w2T_lo[LL * DD * FFD];
__device__ float g_wlmT_hi[(size_t)VV * DD];
__device__ float g_wlmT_lo[(size_t)VV * DD];

// ======================= weight prep =======================
__global__ void prep_qkvT_k(const float* __restrict__ wq,
                            const float* __restrict__ wk,
                            const float* __restrict__ wv) {
    int i = blockIdx.x * blockDim.x + threadIdx.x;
    const int total = LL * 3 * DD * DD;
    if (i >= total) return;
    int d = i % DD;
    int n = (i / DD) % (3 * DD);
    int l = i / (DD * 3 * DD);
    int sel = n / DD;
    int h = (n % DD) / HSZ;
    int e = n % HSZ;
    size_t src = (((size_t)l * HH + h) * DD + d) * HSZ + e;
    float v = (sel == 0) ? wq[src] : (sel == 1) ? wk[src] : wv[src];
    float2 s = tf32split(v);
    g_wqkvT_hi[i] = s.x;
    g_wqkvT_lo[i] = s.y;
}

// generic transpose + split: in[z][K][N] -> out[z][N][K]
__global__ void tsplit_k(const float* __restrict__ in,
                         float* __restrict__ oh, float* __restrict__ ol,
                         int K, int N) {
    __shared__ float tile[32][33];
    size_t zofs = (size_t)blockIdx.z * K * N;
    in += zofs; oh += zofs; ol += zofs;
    int tx = threadIdx.x, ty = threadIdx.y;
    int x = blockIdx.x * 32 + tx;
    int y0 = blockIdx.y * 32;
    #pragma unroll
    for (int j = 0; j < 32; j += 8)
        tile[ty + j][tx] = in[(size_t)(y0 + ty + j) * N + x];
    __syncthreads();
    #pragma unroll
    for (int j = 0; j < 32; j += 8) {
        float v = tile[tx][ty + j];
        float2 s = tf32split(v);
        size_t o = (size_t)(blockIdx.x * 32 + ty + j) * K + y0 + tx;
        oh[o] = s.x;
        ol[o] = s.y;
    }
}

// ======================= embedding =======================
__global__ void embed_k(const int* __restrict__ idx,
                        const float* __restrict__ tok,
                        const float* __restrict__ pos) {
    int i = blockIdx.x * blockDim.x + threadIdx.x;
    if (i >= MM * DD) return;
    int d = i % DD;
    int m = i / DD;
    int t = m % TT;
    g_x[i] = tok[(size_t)idx[m] * DD + d] + pos[t * DD + d];
}

// ======================= layernorm =======================
__global__ void layernorm_k(const float* __restrict__ x,
                            const float* __restrict__ g,
                            const float* __restrict__ b,
                            float* __restrict__ out) {
    int row = blockIdx.x;
    const float* xr = x + (size_t)row * DD;
    int tid = threadIdx.x;  // 256
    float v0 = xr[tid], v1 = xr[tid + 256], v2 = xr[tid + 512];
    float s = v0 + v1 + v2;
    float sq = v0 * v0 + v1 * v1 + v2 * v2;
    __shared__ float shs[8], shq[8];
    #pragma unroll
    for (int o = 16; o; o >>= 1) {
        s  += __shfl_xor_sync(0xffffffffu, s, o);
        sq += __shfl_xor_sync(0xffffffffu, sq, o);
    }
    if ((tid & 31) == 0) { shs[tid >> 5] = s; shq[tid >> 5] = sq; }
    __syncthreads();
    if (tid < 32) {
        s  = (tid < 8) ? shs[tid] : 0.f;
        sq = (tid < 8) ? shq[tid] : 0.f;
        #pragma unroll
        for (int o = 4; o; o >>= 1) {
            s  += __shfl_xor_sync(0xffffffffu, s, o);
            sq += __shfl_xor_sync(0xffffffffu, sq, o);
        }
        if (tid == 0) { shs[0] = s; shq[0] = sq; }
    }
    __syncthreads();
    float mean = shs[0] * (1.f / DD);
    float var  = shq[0] * (1.f / DD) - mean * mean;
    float r = rsqrtf(var + 1e-5f);
    float* o = out + (size_t)row * DD;
    o[tid]       = (v0 - mean) * r * g[tid]       + b[tid];
    o[tid + 256] = (v1 - mean) * r * g[tid + 256] + b[tid + 256];
    o[tid + 512] = (v2 - mean) * r * g[tid + 512] + b[tid + 512];
}

// ======================= mma.sync tf32 GEMM (3xTF32 split) =======================
// C[M,N] = A[M,K] * B^T ; Bhi/Blo are [N][K] tf32 hi/lo. K % 16 == 0.
// EPI: 0 none, 1 bias, 2 bias+relu, 3 bias+residual
// smem per stage (floats): As_hi[128*20] As_lo Bs_hi Bs_lo -> 10240 floats
#define STG_FLOATS 10240
#define GEMM_SMEM_BYTES (2 * STG_FLOATS * 4)

template <int EPI>
__global__ void __launch_bounds__(256)
mma_gemm_k(int M, int N, int K,
           const float* __restrict__ A,
           const float* __restrict__ Bhi, const float* __restrict__ Blo,
           const float* __restrict__ bias, const float* __restrict__ res,
           float* __restrict__ C) {
    extern __shared__ float smem[];
    const int tid = threadIdx.x;
    const int wid = tid >> 5, lid = tid & 31;
    const int g = lid >> 2, t4 = lid & 3;
    const int wm = wid & 1, wn = wid >> 1;          // 2(m) x 4(n) warps
    const int m_off = wm * 64, n_off = wn * 32;

    const int row0 = blockIdx.y * 128, col0 = blockIdx.x * 128;
    const float* Ag  = A   + (size_t)row0 * K;
    const float* Bhg = Bhi + (size_t)col0 * K;
    const float* Blg = Blo + (size_t)col0 * K;

    // per-thread load mapping
    const int ar0 = tid >> 1;                 // A rows: 2 float4 per thread
    const int ac0 = (tid & 1) * 8;            // 8 floats (2 float4) per half-row? no:
    // A tile is 128 rows x 16 floats = 512 float4; thread u-loop covers 2.
    // id = tid + u*256; row = id >> 2; c4 = (id & 3)*4
    float4 aprefetch[2];

    float acc[4][4][4];
    #pragma unroll
    for (int i = 0; i < 4; i++)
        #pragma unroll
        for (int j = 0; j < 4; j++)
            #pragma unroll
            for (int q = 0; q < 4; q++) acc[i][j][q] = 0.f;

    const int KT = K >> 4;
    const uint32_t smem_base = smem_u32(smem);

    // ---- prologue: load tile 0 ----
    {
        #pragma unroll
        for (int u = 0; u < 2; u++) {
            int id = tid + u * 256;
            int r = id >> 2, c = (id & 3) * 4;
            aprefetch[u] = *(const float4*)(Ag + (size_t)r * K + c);
        }
        #pragma unroll
        for (int u = 0; u < 4; u++) {
            int id = tid + u * 256;            // 0..1023
            int mat = id >> 9;                 // 0: hi, 1: lo
            int r = (id >> 2) & 127;
            int c = (id & 3) * 4;
            const float* src = (mat ? Blg : Bhg) + (size_t)r * K + c;
            uint32_t dst = smem_base +
                ((mat ? 7680 : 5120) + r * 20 + c) * 4;
            cp_async16(dst, src);
        }
        asm volatile("cp.async.commit_group;" ::: "memory");
        // split-store A tile 0
        #pragma unroll
        for (int u = 0; u < 2; u++) {
            int id = tid + u * 256;
            int r = id >> 2, c = (id & 3) * 4;
            float* dh = smem + r * 20 + c;
            float* dl = smem + 2560 + r * 20 + c;
            float2 s0 = tf32split(aprefetch[u].x), s1 = tf32split(aprefetch[u].y),
                   s2 = tf32split(aprefetch[u].z), s3 = tf32split(aprefetch[u].w);
            dh[0] = s0.x; dh[1] = s1.x; dh[2] = s2.x; dh[3] = s3.x;
            dl[0] = s0.y; dl[1] = s1.y; dl[2] = s2.y; dl[3] = s3.y;
        }
    }

    for (int t = 0; t < KT; t++) {
        const int cur = t & 1;
        const int nxt = cur ^ 1;
        asm volatile("cp.async.wait_group 0;" ::: "memory");
        __syncthreads();
        // issue next-tile loads
        if (t + 1 < KT) {
            const int tk = (t + 1) * 16;
            #pragma unroll
            for (int u = 0; u < 2; u++) {
                int id = tid + u * 256;
                int r = id >> 2, c = (id & 3) * 4;
                aprefetch[u] = *(const float4*)(Ag + (size_t)r * K + tk + c);
            }
            #pragma unroll
            for (int u = 0; u < 4; u++) {
                int id = tid + u * 256;
                int mat = id >> 9;
                int r = (id >> 2) & 127;
                int c = (id & 3) * 4;
                const float* src = (mat ? Blg : Bhg) + (size_t)r * K + tk + c;
                uint32_t dst = smem_base +
                    (nxt * STG_FLOATS + (mat ? 7680 : 5120) + r * 20 + c) * 4;
                cp_async16(dst, src);
            }
            asm volatile("cp.async.commit_group;" ::: "memory");
        }
        // compute current stage
        {
            const uint32_t* sAh = (const uint32_t*)(smem + cur * STG_FLOATS);
            const uint32_t* sAl = sAh + 2560;
            const uint32_t* sBh = sAh + 5120;
            const uint32_t* sBl = sAh + 7680;
            #pragma unroll
            for (int ks = 0; ks < 2; ks++) {
                uint32_t ah[4][4], al[4][4], bh[4][2], bl[4][2];
                #pragma unroll
                for (int i = 0; i < 4; i++) {
                    int ra = (m_off + i * 16 + g) * 20 + ks * 8 + t4;
                    ah[i][0] = sAh[ra];            ah[i][1] = sAh[ra + 160];
                    ah[i][2] = sAh[ra + 4];        ah[i][3] = sAh[ra + 164];
                    al[i][0] = sAl[ra];            al[i][1] = sAl[ra + 160];
                    al[i][2] = sAl[ra + 4];        al[i][3] = sAl[ra + 164];
                }
                #pragma unroll
                for (int j = 0; j < 4; j++) {
                    int rb = (n_off + j * 8 + g) * 20 + ks * 8 + t4;
                    bh[j][0] = sBh[rb];  bh[j][1] = sBh[rb + 4];
                    bl[j][0] = sBl[rb];  bl[j][1] = sBl[rb + 4];
                }
                #pragma unroll
                for (int i = 0; i < 4; i++)
                    #pragma unroll
                    for (int j = 0; j < 4; j++) {
                        mma_tf32(acc[i][j], ah[i], bh[j]);
                        mma_tf32(acc[i][j], ah[i], bl[j]);
                        mma_tf32(acc[i][j], al[i], bh[j]);
                    }
            }
        }
        // split-store A for next stage
        if (t + 1 < KT) {
            float* base = smem + nxt * STG_FLOATS;
            #pragma unroll
            for (int u = 0; u < 2; u++) {
                int id = tid + u * 256;
                int r = id >> 2, c = (id & 3) * 4;
                float* dh = base + r * 20 + c;
                float* dl = base + 2560 + r * 20 + c;
                float2 s0 = tf32split(aprefetch[u].x), s1 = tf32split(aprefetch[u].y),
                       s2 = tf32split(aprefetch[u].z), s3 = tf32split(aprefetch[u].w);
                dh[0] = s0.x; dh[1] = s1.x; dh[2] = s2.x; dh[3] = s3.x;
                dl[0] = s0.y; dl[1] = s1.y; dl[2] = s2.y; dl[3] = s3.y;
            }
        }
    }

    // ---- epilogue ----
    #pragma unroll
    for (int i = 0; i < 4; i++) {
        int m0 = row0 + m_off + i * 16 + g;
        #pragma unroll
        for (int j = 0; j < 4; j++) {
            int n0 = col0 + n_off + j * 8 + t4 * 2;
            float v0 = acc[i][j][0], v1 = acc[i][j][1];
            float v2 = acc[i][j][2], v3 = acc[i][j][3];
            if (EPI >= 1) {
                float b0 = bias[n0], b1 = bias[n0 + 1];
                v0 += b0; v1 += b1; v2 += b0; v3 += b1;
            }
            if (EPI == 2) {
                v0 = fmaxf(v0, 0.f); v1 = fmaxf(v1, 0.f);
                v2 = fmaxf(v2, 0.f); v3 = fmaxf(v3, 0.f);
            }
            if (EPI == 3) {
                const float* r0p = res + (size_t)m0 * N + n0;
                const float* r1p = res + (size_t)(m0 + 8) * N + n0;
                v0 += r0p[0]; v1 += r0p[1]; v2 += r1p[0]; v3 += r1p[1];
            }
            *(float2*)(C + (size_t)m0 * N + n0)       = make_float2(v0, v1);
            *(float2*)(C + (size_t)(m0 + 8) * N + n0) = make_float2(v2, v3);
        }
    }
}

// ======================= attention (SIMT) =======================
__global__ void __launch_bounds__(256)
attn_scores_k(void) {
    const int bh = blockIdx.z;
    const int b = bh / HH, h = bh % HH;
    const int tqb = blockIdx.y * 64, tsb = blockIdx.x * 64;
    float* Sout = g_scores + (size_t)bh * TT * TT;
    int tid = threadIdx.x;
    int tr = tid >> 4, tc = tid & 15;

    if (tsb > tqb + 63) {
        #pragma unroll
        for (int i = 0; i < 4; i++)
            #pragma unroll
            for (int j = 0; j < 4; j++)
                Sout[(size_t)(tqb + tr * 4 + i) * TT + tsb + tc * 4 + j] = -1e30f;
        return;
    }

    __shared__ float Qs[16][64];
    __shared__ float Ks[16][64];
    const float* Qbase = g_qkv + (size_t)(b * TT + tqb) * (3 * DD) + h * HSZ;
    const float* Kbase = g_qkv + (size_t)(b * TT + tsb) * (3 * DD) + DD + h * HSZ;
    int lr = tid >> 2, lc = (tid & 3) * 4;

    float acc[4][4];
    #pragma unroll
    for (int i = 0; i < 4; i++)
        #pragma unroll
        for (int j = 0; j < 4; j++) acc[i][j] = 0.f;

    for (int k0 = 0; k0 < HSZ; k0 += 16) {
        float4 q = *(const float4*)(Qbase + (size_t)lr * (3 * DD) + k0 + lc);
        Qs[lc + 0][lr] = q.x; Qs[lc + 1][lr] = q.y;
        Qs[lc + 2][lr] = q.z; Qs[lc + 3][lr] = q.w;
        float4 kk = *(const float4*)(Kbase + (size_t)lr * (3 * DD) + k0 + lc);
        Ks[lc + 0][lr] = kk.x; Ks[lc + 1][lr] = kk.y;
        Ks[lc + 2][lr] = kk.z; Ks[lc + 3][lr] = kk.w;
        __syncthreads();
        #pragma unroll
        for (int k = 0; k < 16; k++) {
            float rq[4], rk[4];
            #pragma unroll
            for (int i = 0; i < 4; i++) rq[i] = Qs[k][tr * 4 + i];
            #pragma unroll
            for (int j = 0; j < 4; j++) rk[j] = Ks[k][tc * 4 + j];
            #pragma unroll
            for (int i = 0; i < 4; i++)
                #pragma unroll
                for (int j = 0; j < 4; j++)
                    acc[i][j] += rq[i] * rk[j];
        }
        __syncthreads();
    }

    const float scale = 0.08838834764831845f;
    #pragma unroll
    for (int i = 0; i < 4; i++) {
        int t = tqb + tr * 4 + i;
        #pragma unroll
        for (int j = 0; j < 4; j++) {
            int s = tsb + tc * 4 + j;
            Sout[(size_t)t * TT + s] = (s <= t) ? acc[i][j] * scale : -1e30f;
        }
    }
}

__global__ void softmax_k(void) {
    size_t row = blockIdx.x;
    float* p = g_scores + row * TT;
    int tid = threadIdx.x;
    float v[4];
    #pragma unroll
    for (int i = 0; i < 4; i++) v[i] = p[tid + i * 256];
    float mx = fmaxf(fmaxf(v[0], v[1]), fmaxf(v[2], v[3]));
    __shared__ float sh[8];
    __shared__ float bc;
    #pragma unroll
    for (int o = 16; o; o >>= 1) mx = fmaxf(mx, __shfl_xor_sync(0xffffffffu, mx, o));
    if ((tid & 31) == 0) sh[tid >> 5] = mx;
    __syncthreads();
    if (tid < 32) {
        mx = (tid < 8) ? sh[tid] : -1e30f;
        #pragma unroll
        for (int o = 4; o; o >>= 1) mx = fmaxf(mx, __shfl_xor_sync(0xffffffffu, mx, o));
        if (tid == 0) bc = mx;
    }
    __syncthreads();
    mx = bc;
    float sum = 0.f;
    #pragma unroll
    for (int i = 0; i < 4; i++) { v[i] = __expf(v[i] - mx); sum += v[i]; }
    __syncthreads();
    #pragma unroll
    for (int o = 16; o; o >>= 1) sum += __shfl_xor_sync(0xffffffffu, sum, o);
    if ((tid & 31) == 0) sh[tid >> 5] = sum;
    __syncthreads();
    if (tid < 32) {
        sum = (tid < 8) ? sh[tid] : 0.f;
        #pragma unroll
        for (int o = 4; o; o >>= 1) sum += __shfl_xor_sync(0xffffffffu, sum, o);
        if (tid == 0) bc = sum;
    }
    __syncthreads();
    float inv = 1.f / bc;
    #pragma unroll
    for (int i = 0; i < 4; i++) p[tid + i * 256] = v[i] * inv;
}

__global__ void __launch_bounds__(256)
attn_pv_k(void) {
    const int bh = blockIdx.z;
    const int b = bh / HH, h = bh % HH;
    const int tqb = blockIdx.y * 64, eb = blockIdx.x * 64;
    const float* P = g_scores + (size_t)bh * TT * TT + (size_t)tqb * TT;
    const float* V = g_qkv + (size_t)(b * TT) * (3 * DD) + 2 * DD + h * HSZ + eb;
    int tid = threadIdx.x;
    int tr = tid >> 4, tc = tid & 15;
    int lrP = tid >> 2, lcP = (tid & 3) * 4;
    int lrV = tid >> 4, lcV = (tid & 15) * 4;

    __shared__ float Ps[16][64];
    __shared__ float Vs[16][64];

    float acc[4][4];
    #pragma unroll
    for (int i = 0; i < 4; i++)
        #pragma unroll
        for (int j = 0; j < 4; j++) acc[i][j] = 0.f;

    int kmax = tqb + 64;
    for (int k0 = 0; k0 < kmax; k0 += 16) {
        float4 pv = *(const float4*)(P + (size_t)lrP * TT + k0 + lcP);
        Ps[lcP + 0][lrP] = pv.x; Ps[lcP + 1][lrP] = pv.y;
        Ps[lcP + 2][lrP] = pv.z; Ps[lcP + 3][lrP] = pv.w;
        *(float4*)(&Vs[lrV][lcV]) =
            *(const float4*)(V + (size_t)(k0 + lrV) * (3 * DD) + lcV);
        __syncthreads();
        #pragma unroll
        for (int k = 0; k < 16; k++) {
            float rp[4], rv[4];
            #pragma unroll
            for (int i = 0; i < 4; i++) rp[i] = Ps[k][tr * 4 + i];
            #pragma unroll
            for (int j = 0; j < 4; j++) rv[j] = Vs[k][tc * 4 + j];
            #pragma unroll
            for (int i = 0; i < 4; i++)
                #pragma unroll
                for (int j = 0; j < 4; j++)
                    acc[i][j] += rp[i] * rv[j];
        }
        __syncthreads();
    }

    #pragma unroll
    for (int i = 0; i < 4; i++) {
        int t = tqb + tr * 4 + i;
        #pragma unroll
        for (int j = 0; j < 4; j++) {
            int e = eb + tc * 4 + j;
            g_att[(size_t)(b * TT + t) * DD + h * HSZ + e] = acc[i][j];
        }
    }
}

// ======================= host orchestration =======================
extern "C" void kernel_launch(void* const* d_in, const int* in_sizes, int n_in,
                              void* d_out, int out_size) {
    const int*   idx     = (const int*)d_in[0];
    const float* tok_emb = (const float*)d_in[1];
    const float* pos_emb = (const float*)d_in[2];
    const float* wq      = (const float*)d_in[3];
    const float* wk      = (const float*)d_in[4];
    const float* wv      = (const float*)d_in[5];
    const float* wo      = (const float*)d_in[6];
    const float* bo      = (const float*)d_in[7];
    const float* w1      = (const float*)d_in[8];
    const float* b1      = (const float*)d_in[9];
    const float* w2      = (const float*)d_in[10];
    const float* b2      = (const float*)d_in[11];
    const float* g1      = (const float*)d_in[12];
    const float* be1     = (const float*)d_in[13];
    const float* g2      = (const float*)d_in[14];
    const float* be2     = (const float*)d_in[15];
    const float* wlm     = (const float*)d_in[16];
    const float* blm     = (const float*)d_in[17];
    float* out = (float*)d_out;

    float *px, *ph, *pqkv, *patt, *pff;
    float *pqkvT_h, *pqkvT_l, *pwoT_h, *pwoT_l, *pw1T_h, *pw1T_l,
          *pw2T_h, *pw2T_l, *plmT_h, *plmT_l;
    cudaGetSymbolAddress((void**)&px,   g_x);
    cudaGetSymbolAddress((void**)&ph,   g_h);
    cudaGetSymbolAddress((void**)&pqkv, g_qkv);
    cudaGetSymbolAddress((void**)&patt, g_att);
    cudaGetSymbolAddress((void**)&pff,  g_ff);
    cudaGetSymbolAddress((void**)&pqkvT_h, g_wqkvT_hi);
    cudaGetSymbolAddress((void**)&pqkvT_l, g_wqkvT_lo);
    cudaGetSymbolAddress((void**)&pwoT_h,  g_woT_hi);
    cudaGetSymbolAddress((void**)&pwoT_l,  g_woT_lo);
    cudaGetSymbolAddress((void**)&pw1T_h,  g_w1T_hi);
    cudaGetSymbolAddress((void**)&pw1T_l,  g_w1T_lo);
    cudaGetSymbolAddress((void**)&pw2T_h,  g_w2T_hi);
    cudaGetSymbolAddress((void**)&pw2T_l,  g_w2T_lo);
    cudaGetSymbolAddress((void**)&plmT_h,  g_wlmT_hi);
    cudaGetSymbolAddress((void**)&plmT_l,  g_wlmT_lo);

    cudaFuncSetAttribute(mma_gemm_k<0>, cudaFuncAttributeMaxDynamicSharedMemorySize, GEMM_SMEM_BYTES);
    cudaFuncSetAttribute(mma_gemm_k<1>, cudaFuncAttributeMaxDynamicSharedMemorySize, GEMM_SMEM_BYTES);
    cudaFuncSetAttribute(mma_gemm_k<2>, cudaFuncAttributeMaxDynamicSharedMemorySize, GEMM_SMEM_BYTES);
    cudaFuncSetAttribute(mma_gemm_k<3>, cudaFuncAttributeMaxDynamicSharedMemorySize, GEMM_SMEM_BYTES);

    // weight prep (transpose + tf32 split) + embedding
    {
        int total = LL * 3 * DD * DD;
        prep_qkvT_k<<<(total + 255) / 256, 256>>>(wq, wk, wv);
        dim3 blk(32, 8);
        tsplit_k<<<dim3(DD / 32, DD / 32, LL), blk>>>(wo, pwoT_h, pwoT_l, DD, DD);
        tsplit_k<<<dim3(FFD / 32, DD / 32, LL), blk>>>(w1, pw1T_h, pw1T_l, DD, FFD);
        tsplit_k<<<dim3(DD / 32, FFD / 32, LL), blk>>>(w2, pw2T_h, pw2T_l, FFD, DD);
        tsplit_k<<<dim3(VV / 32, DD / 32, 1), blk>>>(wlm, plmT_h, plmT_l, DD, VV);
        embed_k<<<(MM * DD + 255) / 256, 256>>>(idx, tok_emb, pos_emb);
    }

    for (int l = 0; l < LL; l++) {
        layernorm_k<<<MM, 256>>>(px, g1 + l * DD, be1 + l * DD, ph);
        // qkv: [M, 2304]
        mma_gemm_k<0><<<dim3(3 * DD / 128, MM / 128), 256, GEMM_SMEM_BYTES>>>(
            MM, 3 * DD, DD, ph,
            pqkvT_h + (size_t)l * 3 * DD * DD,
            pqkvT_l + (size_t)l * 3 * DD * DD,
            nullptr, nullptr, pqkv);
        // attention
        attn_scores_k<<<dim3(16, 16, BBATCH * HH), 256>>>();
        softmax_k<<<BBATCH * HH * TT, 256>>>();
        attn_pv_k<<<dim3(2, 16, BBATCH * HH), 256>>>();
        // proj + bias + residual
        mma_gemm_k<3><<<dim3(DD / 128, MM / 128), 256, GEMM_SMEM_BYTES>>>(
            MM, DD, DD, patt,
            pwoT_h + (size_t)l * DD * DD,
            pwoT_l + (size_t)l * DD * DD,
            bo + l * DD, px, px);
        layernorm_k<<<MM, 256>>>(px, g2 + l * DD, be2 + l * DD, ph);
        // ff1: bias + relu
        mma_gemm_k<2><<<dim3(FFD / 128, MM / 128), 256, GEMM_SMEM_BYTES>>>(
            MM, FFD, DD, ph,
            pw1T_h + (size_t)l * FFD * DD,
            pw1T_l + (size_t)l * FFD * DD,
            b1 + l * FFD, nullptr, pff);
        // ff2: bias + residual
        mma_gemm_k<3><<<dim3(DD / 128, MM / 128), 256, GEMM_SMEM_BYTES>>>(
            MM, DD, FFD, pff,
            pw2T_h + (size_t)l * DD * FFD,
            pw2T_l + (size_t)l * DD * FFD,
            b2 + l * DD, px, px);
    }

    // LM head: out = x @ wlm + blm
    mma_gemm_k<1><<<dim3(VV / 128, MM / 128), 256, GEMM_SMEM_BYTES>>>(
        MM, VV, DD, px, plmT_h, plmT_l, blm, nullptr, out);
}

// round 4
// speedup vs baseline: 2.0030x; 1.6780x over previous
#include <cuda_runtime.h>
#include <cuda_fp16.h>
#include <cstdint>

#define DD   768
#define TT   1024
#define BBATCH 4
#define MM   4096          // B*T
#define HH   6
#define HSZ  128
#define FFD  3072
#define VV   32000
#define LL   6

// ======================= helpers =======================
static __device__ __forceinline__ uint32_t smem_u32(const void* p) {
    uint32_t a;
    asm("{ .reg .u64 t; cvta.to.shared.u64 t, %1; cvt.u32.u64 %0, t; }"
        : "=r"(a) : "l"(p));
    return a;
}

static __device__ __forceinline__ void cp_async16(uint32_t dst_smem, const void* src) {
    asm volatile("cp.async.cg.shared.global [%0], [%1], 16;"
                 :: "r"(dst_smem), "l"(src) : "memory");
}

static __device__ __forceinline__ void mma_f16(float* d, const uint32_t* a,
                                               const uint32_t* b) {
    asm volatile(
        "mma.sync.aligned.m16n8k16.row.col.f32.f16.f16.f32 "
        "{%0,%1,%2,%3}, {%4,%5,%6,%7}, {%8,%9}, {%0,%1,%2,%3};"
        : "+f"(d[0]), "+f"(d[1]), "+f"(d[2]), "+f"(d[3])
        : "r"(a[0]), "r"(a[1]), "r"(a[2]), "r"(a[3]), "r"(b[0]), "r"(b[1]));
}

#define LDSM_X4(R0, R1, R2, R3, ADDR) \
    asm volatile("ldmatrix.sync.aligned.m8n8.x4.shared.b16 {%0,%1,%2,%3}, [%4];" \
                 : "=r"(R0), "=r"(R1), "=r"(R2), "=r"(R3) : "r"(ADDR))

static __device__ __forceinline__ void f16split(float a, __half& hi, __half& lo) {
    hi = __float2half_rn(a);
    lo = __float2half_rn(a - __half2float(hi));
}

// ======================= scratch (device globals) =======================
__device__ float g_x[MM * DD];
__device__ float g_h[MM * DD];
__device__ float g_qkv[MM * 3 * DD];
__device__ float g_att[MM * DD];
__device__ float g_ff[MM * FFD];
__device__ float g_scores[(size_t)BBATCH * HH * TT * TT];

// split+transposed weights (B^T layout: [N][K], fp16 hi/lo)
__device__ __half g_wqkvT_hi[LL * 3 * DD * DD];
__device__ __half g_wqkvT_lo[LL * 3 * DD * DD];
__device__ __half g_woT_hi[LL * DD * DD];
__device__ __half g_woT_lo[LL * DD * DD];
__device__ __half g_w1T_hi[LL * FFD * DD];
__device__ __half g_w1T_lo[LL * FFD * DD];
__device__ __half g_w2T_hi[LL * DD * FFD];
__device__ __half g_w2T_lo[LL * DD * FFD];
__device__ __half g_wlmT_hi[(size_t)VV * DD];
__device__ __half g_wlmT_lo[(size_t)VV * DD];

// ======================= weight prep =======================
__global__ void prep_qkvT_k(const float* __restrict__ wq,
                            const float* __restrict__ wk,
                            const float* __restrict__ wv) {
    int i = blockIdx.x * blockDim.x + threadIdx.x;
    const int total = LL * 3 * DD * DD;
    if (i >= total) return;
    int d = i % DD;
    int n = (i / DD) % (3 * DD);
    int l = i / (DD * 3 * DD);
    int sel = n / DD;
    int h = (n % DD) / HSZ;
    int e = n % HSZ;
    size_t src = (((size_t)l * HH + h) * DD + d) * HSZ + e;
    float v = (sel == 0) ? wq[src] : (sel == 1) ? wk[src] : wv[src];
    __half hi, lo;
    f16split(v, hi, lo);
    g_wqkvT_hi[i] = hi;
    g_wqkvT_lo[i] = lo;
}

// transpose + split: in[z][K][N] -> out[z][N][K]
__global__ void tsplit_k(const float* __restrict__ in,
                         __half* __restrict__ oh, __half* __restrict__ ol,
                         int K, int N) {
    __shared__ float tile[32][33];
    size_t zofs = (size_t)blockIdx.z * K * N;
    in += zofs; oh += zofs; ol += zofs;
    int tx = threadIdx.x, ty = threadIdx.y;
    int x = blockIdx.x * 32 + tx;
    int y0 = blockIdx.y * 32;
    #pragma unroll
    for (int j = 0; j < 32; j += 8)
        tile[ty + j][tx] = in[(size_t)(y0 + ty + j) * N + x];
    __syncthreads();
    #pragma unroll
    for (int j = 0; j < 32; j += 8) {
        float v = tile[tx][ty + j];
        __half hi, lo;
        f16split(v, hi, lo);
        size_t o = (size_t)(blockIdx.x * 32 + ty + j) * K + y0 + tx;
        oh[o] = hi;
        ol[o] = lo;
    }
}

// ======================= embedding =======================
__global__ void embed_k(const int* __restrict__ idx,
                        const float* __restrict__ tok,
                        const float* __restrict__ pos) {
    int i = blockIdx.x * blockDim.x + threadIdx.x;
    if (i >= MM * DD) return;
    int d = i % DD;
    int m = i / DD;
    int t = m % TT;
    g_x[i] = tok[(size_t)idx[m] * DD + d] + pos[t * DD + d];
}

// ======================= layernorm =======================
__global__ void layernorm_k(const float* __restrict__ x,
                            const float* __restrict__ g,
                            const float* __restrict__ b,
                            float* __restrict__ out) {
    int row = blockIdx.x;
    const float* xr = x + (size_t)row * DD;
    int tid = threadIdx.x;  // 256
    float v0 = xr[tid], v1 = xr[tid + 256], v2 = xr[tid + 512];
    float s = v0 + v1 + v2;
    float sq = v0 * v0 + v1 * v1 + v2 * v2;
    __shared__ float shs[8], shq[8];
    #pragma unroll
    for (int o = 16; o; o >>= 1) {
        s  += __shfl_xor_sync(0xffffffffu, s, o);
        sq += __shfl_xor_sync(0xffffffffu, sq, o);
    }
    if ((tid & 31) == 0) { shs[tid >> 5] = s; shq[tid >> 5] = sq; }
    __syncthreads();
    if (tid < 32) {
        s  = (tid < 8) ? shs[tid] : 0.f;
        sq = (tid < 8) ? shq[tid] : 0.f;
        #pragma unroll
        for (int o = 4; o; o >>= 1) {
            s  += __shfl_xor_sync(0xffffffffu, s, o);
            sq += __shfl_xor_sync(0xffffffffu, sq, o);
        }
        if (tid == 0) { shs[0] = s; shq[0] = sq; }
    }
    __syncthreads();
    float mean = shs[0] * (1.f / DD);
    float var  = shq[0] * (1.f / DD) - mean * mean;
    float r = rsqrtf(var + 1e-5f);
    float* o = out + (size_t)row * DD;
    o[tid]       = (v0 - mean) * r * g[tid]       + b[tid];
    o[tid + 256] = (v1 - mean) * r * g[tid + 256] + b[tid + 256];
    o[tid + 512] = (v2 - mean) * r * g[tid + 512] + b[tid + 512];
}

// ======================= fp16-split mma GEMM =======================
// C[M,N] = A[M,K] * B^T ; Bhi/Blo are fp16 [N][K] hi/lo. K % 16 == 0.
// EPI: 0 none, 1 bias, 2 bias+relu, 3 bias+residual
// Stage layout (bytes): Ahi[128*48] Alo Bhi Blo ; row stride 48B (16 halves + pad)
#define STAGE_BYTES 24576
#define A_LO_OFF    6144
#define B_HI_OFF    12288
#define B_LO_OFF    18432
#define GEMM_SMEM_BYTES (2 * STAGE_BYTES)

template <int EPI>
__global__ void __launch_bounds__(256)
mma_gemm_k(int M, int N, int K,
           const float* __restrict__ A,
           const __half* __restrict__ Bhi, const __half* __restrict__ Blo,
           const float* __restrict__ bias, const float* __restrict__ res,
           float* __restrict__ C) {
    extern __shared__ __align__(16) char smem[];
    const uint32_t sb = smem_u32(smem);
    const int tid = threadIdx.x;
    const int wid = tid >> 5, lid = tid & 31;
    const int g = lid >> 2, t4 = lid & 3;
    const int wm = wid & 1, wn = wid >> 1;          // 2(m) x 4(n) warps
    const int m_off = wm * 64, n_off = wn * 32;

    const int row0 = blockIdx.y * 128, col0 = blockIdx.x * 128;
    const float*  Ag  = A   + (size_t)row0 * K;
    const __half* Bhg = Bhi + (size_t)col0 * K;
    const __half* Blg = Blo + (size_t)col0 * K;

    // ldmatrix lane addressing
    const int row_off = ((lid >> 3) & 1) * 8 + (lid & 7);
    const int cByte   = (lid >> 4) * 16;
    const uint32_t aHiAddr = sb + (m_off + row_off) * 48 + cByte;
    const uint32_t bHiAddr = sb + B_HI_OFF + (n_off + row_off) * 48 + cByte;

    float acc[4][4][4];
    #pragma unroll
    for (int i = 0; i < 4; i++)
        #pragma unroll
        for (int j = 0; j < 4; j++)
            #pragma unroll
            for (int q = 0; q < 4; q++) acc[i][j][q] = 0.f;

    const int KT = K >> 4;
    float4 apf[2];

    // per-thread load mapping
    // A: id = tid + u*256 (0..511): r = id>>2, c = (id&3)*4 (floats)
    // B: id = tid + u*256 (0..511): mat = id>>8, r = (id>>1)&127, c = (id&1)*8 (halves)

    // ---- prologue: stage 0 ----
    {
        #pragma unroll
        for (int u = 0; u < 2; u++) {
            int id = tid + u * 256;
            int mat = id >> 8;
            int r = (id >> 1) & 127;
            int c = (id & 1) * 8;
            const __half* src = (mat ? Blg : Bhg) + (size_t)r * K + c;
            uint32_t dst = sb + (mat ? B_LO_OFF : B_HI_OFF) + r * 48 + c * 2;
            cp_async16(dst, src);
        }
        asm volatile("cp.async.commit_group;" ::: "memory");
        #pragma unroll
        for (int u = 0; u < 2; u++) {
            int id = tid + u * 256;
            int r = id >> 2, c = (id & 3) * 4;
            float4 v = *(const float4*)(Ag + (size_t)r * K + c);
            __half h0, h1, h2, h3, l0, l1, l2, l3;
            f16split(v.x, h0, l0); f16split(v.y, h1, l1);
            f16split(v.z, h2, l2); f16split(v.w, h3, l3);
            char* base = smem;
            uint2 hv, lv;
            __half2 a01 = __halves2half2(h0, h1), a23 = __halves2half2(h2, h3);
            __half2 b01 = __halves2half2(l0, l1), b23 = __halves2half2(l2, l3);
            hv.x = *(uint32_t*)&a01; hv.y = *(uint32_t*)&a23;
            lv.x = *(uint32_t*)&b01; lv.y = *(uint32_t*)&b23;
            *(uint2*)(base + r * 48 + c * 2)            = hv;
            *(uint2*)(base + A_LO_OFF + r * 48 + c * 2) = lv;
        }
    }

    for (int t = 0; t < KT; t++) {
        const int cur = t & 1;
        const int nxt = cur ^ 1;
        asm volatile("cp.async.wait_group 0;" ::: "memory");
        __syncthreads();
        if (t + 1 < KT) {
            const int tk = (t + 1) * 16;
            #pragma unroll
            for (int u = 0; u < 2; u++) {
                int id = tid + u * 256;
                int r = id >> 2, c = (id & 3) * 4;
                apf[u] = *(const float4*)(Ag + (size_t)r * K + tk + c);
            }
            #pragma unroll
            for (int u = 0; u < 2; u++) {
                int id = tid + u * 256;
                int mat = id >> 8;
                int r = (id >> 1) & 127;
                int c = (id & 1) * 8;
                const __half* src = (mat ? Blg : Bhg) + (size_t)r * K + tk + c;
                uint32_t dst = sb + nxt * STAGE_BYTES +
                               (mat ? B_LO_OFF : B_HI_OFF) + r * 48 + c * 2;
                cp_async16(dst, src);
            }
            asm volatile("cp.async.commit_group;" ::: "memory");
        }
        // ---- compute current stage ----
        {
            uint32_t ah[4][4], al[4][4], bh[4][2], bl[4][2];
            const uint32_t aA = aHiAddr + cur * STAGE_BYTES;
            #pragma unroll
            for (int i = 0; i < 4; i++) {
                LDSM_X4(ah[i][0], ah[i][1], ah[i][2], ah[i][3], aA + i * 768);
                LDSM_X4(al[i][0], al[i][1], al[i][2], al[i][3], aA + A_LO_OFF + i * 768);
            }
            const uint32_t bA = bHiAddr + cur * STAGE_BYTES;
            #pragma unroll
            for (int jp = 0; jp < 2; jp++) {
                LDSM_X4(bh[2 * jp][0], bh[2 * jp + 1][0], bh[2 * jp][1], bh[2 * jp + 1][1],
                        bA + jp * 768);
                LDSM_X4(bl[2 * jp][0], bl[2 * jp + 1][0], bl[2 * jp][1], bl[2 * jp + 1][1],
                        bA + 6144 + jp * 768);
            }
            #pragma unroll
            for (int i = 0; i < 4; i++)
                #pragma unroll
                for (int j = 0; j < 4; j++) {
                    mma_f16(acc[i][j], ah[i], bh[j]);
                    mma_f16(acc[i][j], ah[i], bl[j]);
                    mma_f16(acc[i][j], al[i], bh[j]);
                }
        }
        // split-store A for next stage
        if (t + 1 < KT) {
            char* base = smem + nxt * STAGE_BYTES;
            #pragma unroll
            for (int u = 0; u < 2; u++) {
                int id = tid + u * 256;
                int r = id >> 2, c = (id & 3) * 4;
                __half h0, h1, h2, h3, l0, l1, l2, l3;
                f16split(apf[u].x, h0, l0); f16split(apf[u].y, h1, l1);
                f16split(apf[u].z, h2, l2); f16split(apf[u].w, h3, l3);
                uint2 hv, lv;
                __half2 a01 = __halves2half2(h0, h1), a23 = __halves2half2(h2, h3);
                __half2 b01 = __halves2half2(l0, l1), b23 = __halves2half2(l2, l3);
                hv.x = *(uint32_t*)&a01; hv.y = *(uint32_t*)&a23;
                lv.x = *(uint32_t*)&b01; lv.y = *(uint32_t*)&b23;
                *(uint2*)(base + r * 48 + c * 2)            = hv;
                *(uint2*)(base + A_LO_OFF + r * 48 + c * 2) = lv;
            }
        }
    }

    // ---- epilogue ----
    #pragma unroll
    for (int i = 0; i < 4; i++) {
        int m0 = row0 + m_off + i * 16 + g;
        #pragma unroll
        for (int j = 0; j < 4; j++) {
            int n0 = col0 + n_off + j * 8 + t4 * 2;
            float v0 = acc[i][j][0], v1 = acc[i][j][1];
            float v2 = acc[i][j][2], v3 = acc[i][j][3];
            if (EPI >= 1) {
                float b0 = bias[n0], b1 = bias[n0 + 1];
                v0 += b0; v1 += b1; v2 += b0; v3 += b1;
            }
            if (EPI == 2) {
                v0 = fmaxf(v0, 0.f); v1 = fmaxf(v1, 0.f);
                v2 = fmaxf(v2, 0.f); v3 = fmaxf(v3, 0.f);
            }
            if (EPI == 3) {
                const float* r0p = res + (size_t)m0 * N + n0;
                const float* r1p = res + (size_t)(m0 + 8) * N + n0;
                v0 += r0p[0]; v1 += r0p[1]; v2 += r1p[0]; v3 += r1p[1];
            }
            *(float2*)(C + (size_t)m0 * N + n0)       = make_float2(v0, v1);
            *(float2*)(C + (size_t)(m0 + 8) * N + n0) = make_float2(v2, v3);
        }
    }
}

// ======================= attention (SIMT) =======================
__global__ void __launch_bounds__(256)
attn_scores_k(void) {
    const int bh = blockIdx.z;
    const int b = bh / HH, h = bh % HH;
    const int tqb = blockIdx.y * 64, tsb = blockIdx.x * 64;
    float* Sout = g_scores + (size_t)bh * TT * TT;
    int tid = threadIdx.x;
    int tr = tid >> 4, tc = tid & 15;

    if (tsb > tqb + 63) {
        #pragma unroll
        for (int i = 0; i < 4; i++)
            #pragma unroll
            for (int j = 0; j < 4; j++)
                Sout[(size_t)(tqb + tr * 4 + i) * TT + tsb + tc * 4 + j] = -1e30f;
        return;
    }

    __shared__ float Qs[16][64];
    __shared__ float Ks[16][64];
    const float* Qbase = g_qkv + (size_t)(b * TT + tqb) * (3 * DD) + h * HSZ;
    const float* Kbase = g_qkv + (size_t)(b * TT + tsb) * (3 * DD) + DD + h * HSZ;
    int lr = tid >> 2, lc = (tid & 3) * 4;

    float acc[4][4];
    #pragma unroll
    for (int i = 0; i < 4; i++)
        #pragma unroll
        for (int j = 0; j < 4; j++) acc[i][j] = 0.f;

    for (int k0 = 0; k0 < HSZ; k0 += 16) {
        float4 q = *(const float4*)(Qbase + (size_t)lr * (3 * DD) + k0 + lc);
        Qs[lc + 0][lr] = q.x; Qs[lc + 1][lr] = q.y;
        Qs[lc + 2][lr] = q.z; Qs[lc + 3][lr] = q.w;
        float4 kk = *(const float4*)(Kbase + (size_t)lr * (3 * DD) + k0 + lc);
        Ks[lc + 0][lr] = kk.x; Ks[lc + 1][lr] = kk.y;
        Ks[lc + 2][lr] = kk.z; Ks[lc + 3][lr] = kk.w;
        __syncthreads();
        #pragma unroll
        for (int k = 0; k < 16; k++) {
            float rq[4], rk[4];
            #pragma unroll
            for (int i = 0; i < 4; i++) rq[i] = Qs[k][tr * 4 + i];
            #pragma unroll
            for (int j = 0; j < 4; j++) rk[j] = Ks[k][tc * 4 + j];
            #pragma unroll
            for (int i = 0; i < 4; i++)
                #pragma unroll
                for (int j = 0; j < 4; j++)
                    acc[i][j] += rq[i] * rk[j];
        }
        __syncthreads();
    }

    const float scale = 0.08838834764831845f;
    #pragma unroll
    for (int i = 0; i < 4; i++) {
        int t = tqb + tr * 4 + i;
        #pragma unroll
        for (int j = 0; j < 4; j++) {
            int s = tsb + tc * 4 + j;
            Sout[(size_t)t * TT + s] = (s <= t) ? acc[i][j] * scale : -1e30f;
        }
    }
}

__global__ void softmax_k(void) {
    size_t row = blockIdx.x;
    float* p = g_scores + row * TT;
    int tid = threadIdx.x;
    float v[4];
    #pragma unroll
    for (int i = 0; i < 4; i++) v[i] = p[tid + i * 256];
    float mx = fmaxf(fmaxf(v[0], v[1]), fmaxf(v[2], v[3]));
    __shared__ float sh[8];
    __shared__ float bc;
    #pragma unroll
    for (int o = 16; o; o >>= 1) mx = fmaxf(mx, __shfl_xor_sync(0xffffffffu, mx, o));
    if ((tid & 31) == 0) sh[tid >> 5] = mx;
    __syncthreads();
    if (tid < 32) {
        mx = (tid < 8) ? sh[tid] : -1e30f;
        #pragma unroll
        for (int o = 4; o; o >>= 1) mx = fmaxf(mx, __shfl_xor_sync(0xffffffffu, mx, o));
        if (tid == 0) bc = mx;
    }
    __syncthreads();
    mx = bc;
    float sum = 0.f;
    #pragma unroll
    for (int i = 0; i < 4; i++) { v[i] = __expf(v[i] - mx); sum += v[i]; }
    __syncthreads();
    #pragma unroll
    for (int o = 16; o; o >>= 1) sum += __shfl_xor_sync(0xffffffffu, sum, o);
    if ((tid & 31) == 0) sh[tid >> 5] = sum;
    __syncthreads();
    if (tid < 32) {
        sum = (tid < 8) ? sh[tid] : 0.f;
        #pragma unroll
        for (int o = 4; o; o >>= 1) sum += __shfl_xor_sync(0xffffffffu, sum, o);
        if (tid == 0) bc = sum;
    }
    __syncthreads();
    float inv = 1.f / bc;
    #pragma unroll
    for (int i = 0; i < 4; i++) p[tid + i * 256] = v[i] * inv;
}

__global__ void __launch_bounds__(256)
attn_pv_k(void) {
    const int bh = blockIdx.z;
    const int b = bh / HH, h = bh % HH;
    const int tqb = blockIdx.y * 64, eb = blockIdx.x * 64;
    const float* P = g_scores + (size_t)bh * TT * TT + (size_t)tqb * TT;
    const float* V = g_qkv + (size_t)(b * TT) * (3 * DD) + 2 * DD + h * HSZ + eb;
    int tid = threadIdx.x;
    int tr = tid >> 4, tc = tid & 15;
    int lrP = tid >> 2, lcP = (tid & 3) * 4;
    int lrV = tid >> 4, lcV = (tid & 15) * 4;

    __shared__ float Ps[16][64];
    __shared__ float Vs[16][64];

    float acc[4][4];
    #pragma unroll
    for (int i = 0; i < 4; i++)
        #pragma unroll
        for (int j = 0; j < 4; j++) acc[i][j] = 0.f;

    int kmax = tqb + 64;
    for (int k0 = 0; k0 < kmax; k0 += 16) {
        float4 pv = *(const float4*)(P + (size_t)lrP * TT + k0 + lcP);
        Ps[lcP + 0][lrP] = pv.x; Ps[lcP + 1][lrP] = pv.y;
        Ps[lcP + 2][lrP] = pv.z; Ps[lcP + 3][lrP] = pv.w;
        *(float4*)(&Vs[lrV][lcV]) =
            *(const float4*)(V + (size_t)(k0 + lrV) * (3 * DD) + lcV);
        __syncthreads();
        #pragma unroll
        for (int k = 0; k < 16; k++) {
            float rp[4], rv[4];
            #pragma unroll
            for (int i = 0; i < 4; i++) rp[i] = Ps[k][tr * 4 + i];
            #pragma unroll
            for (int j = 0; j < 4; j++) rv[j] = Vs[k][tc * 4 + j];
            #pragma unroll
            for (int i = 0; i < 4; i++)
                #pragma unroll
                for (int j = 0; j < 4; j++)
                    acc[i][j] += rp[i] * rv[j];
        }
        __syncthreads();
    }

    #pragma unroll
    for (int i = 0; i < 4; i++) {
        int t = tqb + tr * 4 + i;
        #pragma unroll
        for (int j = 0; j < 4; j++) {
            int e = eb + tc * 4 + j;
            g_att[(size_t)(b * TT + t) * DD + h * HSZ + e] = acc[i][j];
        }
    }
}

// ======================= host orchestration =======================
extern "C" void kernel_launch(void* const* d_in, const int* in_sizes, int n_in,
                              void* d_out, int out_size) {
    const int*   idx     = (const int*)d_in[0];
    const float* tok_emb = (const float*)d_in[1];
    const float* pos_emb = (const float*)d_in[2];
    const float* wq      = (const float*)d_in[3];
    const float* wk      = (const float*)d_in[4];
    const float* wv      = (const float*)d_in[5];
    const float* wo      = (const float*)d_in[6];
    const float* bo      = (const float*)d_in[7];
    const float* w1      = (const float*)d_in[8];
    const float* b1      = (const float*)d_in[9];
    const float* w2      = (const float*)d_in[10];
    const float* b2      = (const float*)d_in[11];
    const float* g1      = (const float*)d_in[12];
    const float* be1     = (const float*)d_in[13];
    const float* g2      = (const float*)d_in[14];
    const float* be2     = (const float*)d_in[15];
    const float* wlm     = (const float*)d_in[16];
    const float* blm     = (const float*)d_in[17];
    float* out = (float*)d_out;

    float *px, *ph, *pqkv, *patt, *pff;
    __half *pqkvT_h, *pqkvT_l, *pwoT_h, *pwoT_l, *pw1T_h, *pw1T_l,
           *pw2T_h, *pw2T_l, *plmT_h, *plmT_l;
    cudaGetSymbolAddress((void**)&px,   g_x);
    cudaGetSymbolAddress((void**)&ph,   g_h);
    cudaGetSymbolAddress((void**)&pqkv, g_qkv);
    cudaGetSymbolAddress((void**)&patt, g_att);
    cudaGetSymbolAddress((void**)&pff,  g_ff);
    cudaGetSymbolAddress((void**)&pqkvT_h, g_wqkvT_hi);
    cudaGetSymbolAddress((void**)&pqkvT_l, g_wqkvT_lo);
    cudaGetSymbolAddress((void**)&pwoT_h,  g_woT_hi);
    cudaGetSymbolAddress((void**)&pwoT_l,  g_woT_lo);
    cudaGetSymbolAddress((void**)&pw1T_h,  g_w1T_hi);
    cudaGetSymbolAddress((void**)&pw1T_l,  g_w1T_lo);
    cudaGetSymbolAddress((void**)&pw2T_h,  g_w2T_hi);
    cudaGetSymbolAddress((void**)&pw2T_l,  g_w2T_lo);
    cudaGetSymbolAddress((void**)&plmT_h,  g_wlmT_hi);
    cudaGetSymbolAddress((void**)&plmT_l,  g_wlmT_lo);

    cudaFuncSetAttribute(mma_gemm_k<0>, cudaFuncAttributeMaxDynamicSharedMemorySize, GEMM_SMEM_BYTES);
    cudaFuncSetAttribute(mma_gemm_k<1>, cudaFuncAttributeMaxDynamicSharedMemorySize, GEMM_SMEM_BYTES);
    cudaFuncSetAttribute(mma_gemm_k<2>, cudaFuncAttributeMaxDynamicSharedMemorySize, GEMM_SMEM_BYTES);
    cudaFuncSetAttribute(mma_gemm_k<3>, cudaFuncAttributeMaxDynamicSharedMemorySize, GEMM_SMEM_BYTES);

    // weight prep (transpose + fp16 split) + embedding
    {
        int total = LL * 3 * DD * DD;
        prep_qkvT_k<<<(total + 255) / 256, 256>>>(wq, wk, wv);
        dim3 blk(32, 8);
        tsplit_k<<<dim3(DD / 32, DD / 32, LL), blk>>>(wo, pwoT_h, pwoT_l, DD, DD);
        tsplit_k<<<dim3(FFD / 32, DD / 32, LL), blk>>>(w1, pw1T_h, pw1T_l, DD, FFD);
        tsplit_k<<<dim3(DD / 32, FFD / 32, LL), blk>>>(w2, pw2T_h, pw2T_l, FFD, DD);
        tsplit_k<<<dim3(VV / 32, DD / 32, 1), blk>>>(wlm, plmT_h, plmT_l, DD, VV);
        embed_k<<<(MM * DD + 255) / 256, 256>>>(idx, tok_emb, pos_emb);
    }

    for (int l = 0; l < LL; l++) {
        layernorm_k<<<MM, 256>>>(px, g1 + l * DD, be1 + l * DD, ph);
        // qkv: [M, 2304]
        mma_gemm_k<0><<<dim3(3 * DD / 128, MM / 128), 256, GEMM_SMEM_BYTES>>>(
            MM, 3 * DD, DD, ph,
            pqkvT_h + (size_t)l * 3 * DD * DD,
            pqkvT_l + (size_t)l * 3 * DD * DD,
            nullptr, nullptr, pqkv);
        // attention
        attn_scores_k<<<dim3(16, 16, BBATCH * HH), 256>>>();
        softmax_k<<<BBATCH * HH * TT, 256>>>();
        attn_pv_k<<<dim3(2, 16, BBATCH * HH), 256>>>();
        // proj + bias + residual
        mma_gemm_k<3><<<dim3(DD / 128, MM / 128), 256, GEMM_SMEM_BYTES>>>(
            MM, DD, DD, patt,
            pwoT_h + (size_t)l * DD * DD,
            pwoT_l + (size_t)l * DD * DD,
            bo + l * DD, px, px);
        layernorm_k<<<MM, 256>>>(px, g2 + l * DD, be2 + l * DD, ph);
        // ff1: bias + relu
        mma_gemm_k<2><<<dim3(FFD / 128, MM / 128), 256, GEMM_SMEM_BYTES>>>(
            MM, FFD, DD, ph,
            pw1T_h + (size_t)l * FFD * DD,
            pw1T_l + (size_t)l * FFD * DD,
            b1 + l * FFD, nullptr, pff);
        // ff2: bias + residual
        mma_gemm_k<3><<<dim3(DD / 128, MM / 128), 256, GEMM_SMEM_BYTES>>>(
            MM, DD, FFD, pff,
            pw2T_h + (size_t)l * DD * FFD,
            pw2T_l + (size_t)l * DD * FFD,
            b2 + l * DD, px, px);
    }

    // LM head: out = x @ wlm + blm
    mma_gemm_k<1><<<dim3(VV / 128, MM / 128), 256, GEMM_SMEM_BYTES>>>(
        MM, VV, DD, px, plmT_h, plmT_l, blm, nullptr, out);
}

// round 5
// speedup vs baseline: 2.2616x; 1.1291x over previous
#include <cuda_runtime.h>
#include <cuda_fp16.h>
#include <cstdint>

#define DD   768
#define TT   1024
#define BBATCH 4
#define MM   4096          // B*T
#define HH   6
#define HSZ  128
#define FFD  3072
#define VV   32000
#define LL   6

// ======================= helpers =======================
static __device__ __forceinline__ uint32_t smem_u32(const void* p) {
    uint32_t a;
    asm("{ .reg .u64 t; cvta.to.shared.u64 t, %1; cvt.u32.u64 %0, t; }"
        : "=r"(a) : "l"(p));
    return a;
}

static __device__ __forceinline__ void cp_async16(uint32_t dst_smem, const void* src) {
    asm volatile("cp.async.cg.shared.global [%0], [%1], 16;"
                 :: "r"(dst_smem), "l"(src) : "memory");
}

static __device__ __forceinline__ void mma_f16(float* d, const uint32_t* a,
                                               const uint32_t* b) {
    asm volatile(
        "mma.sync.aligned.m16n8k16.row.col.f32.f16.f16.f32 "
        "{%0,%1,%2,%3}, {%4,%5,%6,%7}, {%8,%9}, {%0,%1,%2,%3};"
        : "+f"(d[0]), "+f"(d[1]), "+f"(d[2]), "+f"(d[3])
        : "r"(a[0]), "r"(a[1]), "r"(a[2]), "r"(a[3]), "r"(b[0]), "r"(b[1]));
}

#define LDSM_X4(R0, R1, R2, R3, ADDR) \
    asm volatile("ldmatrix.sync.aligned.m8n8.x4.shared.b16 {%0,%1,%2,%3}, [%4];" \
                 : "=r"(R0), "=r"(R1), "=r"(R2), "=r"(R3) : "r"(ADDR))

static __device__ __forceinline__ void f16split(float a, __half& hi, __half& lo) {
    hi = __float2half_rn(a);
    lo = __float2half_rn(a - __half2float(hi));
}

static __device__ __forceinline__ uint32_t pack_h2(__half a, __half b) {
    __half2 h = __halves2half2(a, b);
    return *(uint32_t*)&h;
}

// ======================= scratch (device globals) =======================
__device__ float g_x[MM * DD];
__device__ float g_h[MM * DD];
__device__ float g_att[MM * DD];
__device__ float g_ff[MM * FFD];

// qkv split storage: [sel(3)][bh(24)] ; q,k: [t][e] (128 halves/row); v: [e][t]
// stride per (sel,bh) slab = 1024*128 = 131072 = 1<<17
__device__ __half g_qkvh[3 * 24 * TT * HSZ];
__device__ __half g_qkvl[3 * 24 * TT * HSZ];

// split+transposed weights (B^T layout: [N][K], fp16 hi/lo)
__device__ __half g_wqkvT_hi[LL * 3 * DD * DD];
__device__ __half g_wqkvT_lo[LL * 3 * DD * DD];
__device__ __half g_woT_hi[LL * DD * DD];
__device__ __half g_woT_lo[LL * DD * DD];
__device__ __half g_w1T_hi[LL * FFD * DD];
__device__ __half g_w1T_lo[LL * FFD * DD];
__device__ __half g_w2T_hi[LL * DD * FFD];
__device__ __half g_w2T_lo[LL * DD * FFD];
__device__ __half g_wlmT_hi[(size_t)VV * DD];
__device__ __half g_wlmT_lo[(size_t)VV * DD];

// ======================= weight prep =======================
__global__ void prep_qkvT_k(const float* __restrict__ wq,
                            const float* __restrict__ wk,
                            const float* __restrict__ wv) {
    int i = blockIdx.x * blockDim.x + threadIdx.x;
    const int total = LL * 3 * DD * DD;
    if (i >= total) return;
    int d = i % DD;
    int n = (i / DD) % (3 * DD);
    int l = i / (DD * 3 * DD);
    int sel = n / DD;
    int h = (n % DD) / HSZ;
    int e = n % HSZ;
    size_t src = (((size_t)l * HH + h) * DD + d) * HSZ + e;
    float v = (sel == 0) ? wq[src] : (sel == 1) ? wk[src] : wv[src];
    __half hi, lo;
    f16split(v, hi, lo);
    g_wqkvT_hi[i] = hi;
    g_wqkvT_lo[i] = lo;
}

// transpose + split: in[z][K][N] -> out[z][N][K]
__global__ void tsplit_k(const float* __restrict__ in,
                         __half* __restrict__ oh, __half* __restrict__ ol,
                         int K, int N) {
    __shared__ float tile[32][33];
    size_t zofs = (size_t)blockIdx.z * K * N;
    in += zofs; oh += zofs; ol += zofs;
    int tx = threadIdx.x, ty = threadIdx.y;
    int x = blockIdx.x * 32 + tx;
    int y0 = blockIdx.y * 32;
    #pragma unroll
    for (int j = 0; j < 32; j += 8)
        tile[ty + j][tx] = in[(size_t)(y0 + ty + j) * N + x];
    __syncthreads();
    #pragma unroll
    for (int j = 0; j < 32; j += 8) {
        float v = tile[tx][ty + j];
        __half hi, lo;
        f16split(v, hi, lo);
        size_t o = (size_t)(blockIdx.x * 32 + ty + j) * K + y0 + tx;
        oh[o] = hi;
        ol[o] = lo;
    }
}

// ======================= embedding =======================
__global__ void embed_k(const int* __restrict__ idx,
                        const float* __restrict__ tok,
                        const float* __restrict__ pos) {
    int i = blockIdx.x * blockDim.x + threadIdx.x;
    if (i >= MM * DD) return;
    int d = i % DD;
    int m = i / DD;
    int t = m % TT;
    g_x[i] = tok[(size_t)idx[m] * DD + d] + pos[t * DD + d];
}

// ======================= layernorm =======================
__global__ void layernorm_k(const float* __restrict__ x,
                            const float* __restrict__ g,
                            const float* __restrict__ b,
                            float* __restrict__ out) {
    int row = blockIdx.x;
    const float* xr = x + (size_t)row * DD;
    int tid = threadIdx.x;  // 256
    float v0 = xr[tid], v1 = xr[tid + 256], v2 = xr[tid + 512];
    float s = v0 + v1 + v2;
    float sq = v0 * v0 + v1 * v1 + v2 * v2;
    __shared__ float shs[8], shq[8];
    #pragma unroll
    for (int o = 16; o; o >>= 1) {
        s  += __shfl_xor_sync(0xffffffffu, s, o);
        sq += __shfl_xor_sync(0xffffffffu, sq, o);
    }
    if ((tid & 31) == 0) { shs[tid >> 5] = s; shq[tid >> 5] = sq; }
    __syncthreads();
    if (tid < 32) {
        s  = (tid < 8) ? shs[tid] : 0.f;
        sq = (tid < 8) ? shq[tid] : 0.f;
        #pragma unroll
        for (int o = 4; o; o >>= 1) {
            s  += __shfl_xor_sync(0xffffffffu, s, o);
            sq += __shfl_xor_sync(0xffffffffu, sq, o);
        }
        if (tid == 0) { shs[0] = s; shq[0] = sq; }
    }
    __syncthreads();
    float mean = shs[0] * (1.f / DD);
    float var  = shq[0] * (1.f / DD) - mean * mean;
    float r = rsqrtf(var + 1e-5f);
    float* o = out + (size_t)row * DD;
    o[tid]       = (v0 - mean) * r * g[tid]       + b[tid];
    o[tid + 256] = (v1 - mean) * r * g[tid + 256] + b[tid + 256];
    o[tid + 512] = (v2 - mean) * r * g[tid + 512] + b[tid + 512];
}

// ======================= fp16-split mma GEMM =======================
// C[M,N] = A[M,K] * B^T ; Bhi/Blo are fp16 [N][K] hi/lo. K % 16 == 0.
// EPI: 0 none, 1 bias, 2 bias+relu, 3 bias+residual, 4 qkv-split output
#define STAGE_BYTES 24576
#define A_LO_OFF    6144
#define B_HI_OFF    12288
#define B_LO_OFF    18432
#define GEMM_SMEM_BYTES (2 * STAGE_BYTES)

template <int EPI>
__global__ void __launch_bounds__(256)
mma_gemm_k(int M, int N, int K,
           const float* __restrict__ A,
           const __half* __restrict__ Bhi, const __half* __restrict__ Blo,
           const float* __restrict__ bias, const float* __restrict__ res,
           float* __restrict__ C,
           __half* __restrict__ outh, __half* __restrict__ outl) {
    extern __shared__ __align__(16) char smem[];
    const uint32_t sb = smem_u32(smem);
    const int tid = threadIdx.x;
    const int wid = tid >> 5, lid = tid & 31;
    const int g = lid >> 2, t4 = lid & 3;
    const int wm = wid & 1, wn = wid >> 1;          // 2(m) x 4(n) warps
    const int m_off = wm * 64, n_off = wn * 32;

    const int row0 = blockIdx.y * 128, col0 = blockIdx.x * 128;
    const float*  Ag  = A   + (size_t)row0 * K;
    const __half* Bhg = Bhi + (size_t)col0 * K;
    const __half* Blg = Blo + (size_t)col0 * K;

    const int row_off = ((lid >> 3) & 1) * 8 + (lid & 7);
    const int cByte   = (lid >> 4) * 16;
    const uint32_t aHiAddr = sb + (m_off + row_off) * 48 + cByte;
    const uint32_t bHiAddr = sb + B_HI_OFF + (n_off + row_off) * 48 + cByte;

    float acc[4][4][4];
    #pragma unroll
    for (int i = 0; i < 4; i++)
        #pragma unroll
        for (int j = 0; j < 4; j++)
            #pragma unroll
            for (int q = 0; q < 4; q++) acc[i][j][q] = 0.f;

    const int KT = K >> 4;
    float4 apf[2];

    // ---- prologue: stage 0 ----
    {
        #pragma unroll
        for (int u = 0; u < 2; u++) {
            int id = tid + u * 256;
            int mat = id >> 8;
            int r = (id >> 1) & 127;
            int c = (id & 1) * 8;
            const __half* src = (mat ? Blg : Bhg) + (size_t)r * K + c;
            uint32_t dst = sb + (mat ? B_LO_OFF : B_HI_OFF) + r * 48 + c * 2;
            cp_async16(dst, src);
        }
        asm volatile("cp.async.commit_group;" ::: "memory");
        #pragma unroll
        for (int u = 0; u < 2; u++) {
            int id = tid + u * 256;
            int r = id >> 2, c = (id & 3) * 4;
            float4 v = *(const float4*)(Ag + (size_t)r * K + c);
            __half h0, h1, h2, h3, l0, l1, l2, l3;
            f16split(v.x, h0, l0); f16split(v.y, h1, l1);
            f16split(v.z, h2, l2); f16split(v.w, h3, l3);
            char* base = smem;
            uint2 hv, lv;
            hv.x = pack_h2(h0, h1); hv.y = pack_h2(h2, h3);
            lv.x = pack_h2(l0, l1); lv.y = pack_h2(l2, l3);
            *(uint2*)(base + r * 48 + c * 2)            = hv;
            *(uint2*)(base + A_LO_OFF + r * 48 + c * 2) = lv;
        }
    }

    for (int t = 0; t < KT; t++) {
        const int cur = t & 1;
        const int nxt = cur ^ 1;
        asm volatile("cp.async.wait_group 0;" ::: "memory");
        __syncthreads();
        if (t + 1 < KT) {
            const int tk = (t + 1) * 16;
            #pragma unroll
            for (int u = 0; u < 2; u++) {
                int id = tid + u * 256;
                int r = id >> 2, c = (id & 3) * 4;
                apf[u] = *(const float4*)(Ag + (size_t)r * K + tk + c);
            }
            #pragma unroll
            for (int u = 0; u < 2; u++) {
                int id = tid + u * 256;
                int mat = id >> 8;
                int r = (id >> 1) & 127;
                int c = (id & 1) * 8;
                const __half* src = (mat ? Blg : Bhg) + (size_t)r * K + tk + c;
                uint32_t dst = sb + nxt * STAGE_BYTES +
                               (mat ? B_LO_OFF : B_HI_OFF) + r * 48 + c * 2;
                cp_async16(dst, src);
            }
            asm volatile("cp.async.commit_group;" ::: "memory");
        }
        // ---- compute current stage ----
        {
            uint32_t ah[4][4], al[4][4], bh[4][2], bl[4][2];
            const uint32_t aA = aHiAddr + cur * STAGE_BYTES;
            #pragma unroll
            for (int i = 0; i < 4; i++) {
                LDSM_X4(ah[i][0], ah[i][1], ah[i][2], ah[i][3], aA + i * 768);
                LDSM_X4(al[i][0], al[i][1], al[i][2], al[i][3], aA + A_LO_OFF + i * 768);
            }
            const uint32_t bA = bHiAddr + cur * STAGE_BYTES;
            #pragma unroll
            for (int jp = 0; jp < 2; jp++) {
                LDSM_X4(bh[2 * jp][0], bh[2 * jp + 1][0], bh[2 * jp][1], bh[2 * jp + 1][1],
                        bA + jp * 768);
                LDSM_X4(bl[2 * jp][0], bl[2 * jp + 1][0], bl[2 * jp][1], bl[2 * jp + 1][1],
                        bA + 6144 + jp * 768);
            }
            #pragma unroll
            for (int i = 0; i < 4; i++)
                #pragma unroll
                for (int j = 0; j < 4; j++) {
                    mma_f16(acc[i][j], ah[i], bh[j]);
                    mma_f16(acc[i][j], ah[i], bl[j]);
                    mma_f16(acc[i][j], al[i], bh[j]);
                }
        }
        if (t + 1 < KT) {
            char* base = smem + nxt * STAGE_BYTES;
            #pragma unroll
            for (int u = 0; u < 2; u++) {
                int id = tid + u * 256;
                int r = id >> 2, c = (id & 3) * 4;
                __half h0, h1, h2, h3, l0, l1, l2, l3;
                f16split(apf[u].x, h0, l0); f16split(apf[u].y, h1, l1);
                f16split(apf[u].z, h2, l2); f16split(apf[u].w, h3, l3);
                uint2 hv, lv;
                hv.x = pack_h2(h0, h1); hv.y = pack_h2(h2, h3);
                lv.x = pack_h2(l0, l1); lv.y = pack_h2(l2, l3);
                *(uint2*)(base + r * 48 + c * 2)            = hv;
                *(uint2*)(base + A_LO_OFF + r * 48 + c * 2) = lv;
            }
        }
    }

    // ---- epilogue ----
    #pragma unroll
    for (int i = 0; i < 4; i++) {
        int m0 = row0 + m_off + i * 16 + g;
        #pragma unroll
        for (int j = 0; j < 4; j++) {
            int n0 = col0 + n_off + j * 8 + t4 * 2;
            float v0 = acc[i][j][0], v1 = acc[i][j][1];
            float v2 = acc[i][j][2], v3 = acc[i][j][3];
            if (EPI == 4) {
                // qkv split: q,k -> [sel*24+bh][t][e]; v -> [48+bh][e][t]
                #pragma unroll
                for (int q = 0; q < 4; q++) {
                    int m = m0 + (q >> 1) * 8;
                    int n = n0 + (q & 1);
                    float v = (q == 0) ? v0 : (q == 1) ? v1 : (q == 2) ? v2 : v3;
                    int sel = n / DD;
                    int h = (n % DD) >> 7;
                    int e = n & 127;
                    int b = m >> 10;
                    int tt = m & 1023;
                    int bh6 = b * HH + h;
                    size_t o;
                    if (sel < 2) o = ((size_t)(sel * 24 + bh6) << 17) + tt * 128 + e;
                    else         o = ((size_t)(48 + bh6) << 17) + (size_t)e * 1024 + tt;
                    __half hi, lo;
                    f16split(v, hi, lo);
                    outh[o] = hi;
                    outl[o] = lo;
                }
                continue;
            }
            if (EPI >= 1) {
                float b0 = bias[n0], b1 = bias[n0 + 1];
                v0 += b0; v1 += b1; v2 += b0; v3 += b1;
            }
            if (EPI == 2) {
                v0 = fmaxf(v0, 0.f); v1 = fmaxf(v1, 0.f);
                v2 = fmaxf(v2, 0.f); v3 = fmaxf(v3, 0.f);
            }
            if (EPI == 3) {
                const float* r0p = res + (size_t)m0 * N + n0;
                const float* r1p = res + (size_t)(m0 + 8) * N + n0;
                v0 += r0p[0]; v1 += r0p[1]; v2 += r1p[0]; v3 += r1p[1];
            }
            *(float2*)(C + (size_t)m0 * N + n0)       = make_float2(v0, v1);
            *(float2*)(C + (size_t)(m0 + 8) * N + n0) = make_float2(v2, v3);
        }
    }
}

// ======================= fused flash attention (fp16-split tensor cores) ===
// grid: x = qtile (16, reversed), y = bh (24); 128 threads (4 warps, m16 each)
// smem: Qh Ql [64][272B] ; Kh Kl [64][272B] ; Vh Vl [128][144B] (V transposed)
#define AQ_H 0
#define AQ_L 17408
#define AK_H 34816
#define AK_L 52224
#define AV_H 69632
#define AV_L 88064
#define ATT_SMEM 106496

__global__ void __launch_bounds__(128)
flash_attn_k(const __half* __restrict__ qkvh, const __half* __restrict__ qkvl,
             float* __restrict__ att) {
    extern __shared__ __align__(16) char smem[];
    const uint32_t sb = smem_u32(smem);
    const int bh = blockIdx.y;
    const int qt = 15 - blockIdx.x;
    const int tid = threadIdx.x;
    const int wid = tid >> 5, lid = tid & 31;
    const int g = lid >> 2, t4 = lid & 3;
    const int row_off = lid & 15;
    const int half16 = (lid >> 4) * 16;

    // ---- load Q tile (64 rows x 128 halves, hi+lo) ----
    const __half* qh = qkvh + ((size_t)bh << 17) + qt * 64 * 128;
    const __half* ql = qkvl + ((size_t)bh << 17) + qt * 64 * 128;
    #pragma unroll
    for (int it = 0; it < 8; it++) {
        int id = tid + it * 128;
        int r = id >> 4, cb = id & 15;
        cp_async16(sb + AQ_H + r * 272 + cb * 16, qh + r * 128 + cb * 8);
        cp_async16(sb + AQ_L + r * 272 + cb * 16, ql + r * 128 + cb * 8);
    }
    asm volatile("cp.async.commit_group;" ::: "memory");

    float S[8][4];
    float Oa[16][4];
    #pragma unroll
    for (int nb = 0; nb < 16; nb++)
        #pragma unroll
        for (int q = 0; q < 4; q++) Oa[nb][q] = 0.f;
    float m0 = -1e30f, m1 = -1e30f, l0 = 0.f, l1 = 0.f;
    const float scale = 0.08838834764831845f;

    const __half* kbh = qkvh + ((size_t)(24 + bh) << 17);
    const __half* kbl = qkvl + ((size_t)(24 + bh) << 17);
    const __half* vbh = qkvh + ((size_t)(48 + bh) << 17);
    const __half* vbl = qkvl + ((size_t)(48 + bh) << 17);

    for (int kt = 0; kt <= qt; kt++) {
        // ---- load K (64x128) and V^T (128x64) ----
        const __half* kh = kbh + kt * 64 * 128;
        const __half* kl = kbl + kt * 64 * 128;
        #pragma unroll
        for (int it = 0; it < 8; it++) {
            int id = tid + it * 128;
            int r = id >> 4, cb = id & 15;
            cp_async16(sb + AK_H + r * 272 + cb * 16, kh + r * 128 + cb * 8);
            cp_async16(sb + AK_L + r * 272 + cb * 16, kl + r * 128 + cb * 8);
        }
        #pragma unroll
        for (int it = 0; it < 8; it++) {
            int id = tid + it * 128;
            int e = id >> 3, cb = id & 7;
            cp_async16(sb + AV_H + e * 144 + cb * 16,
                       vbh + (size_t)e * 1024 + kt * 64 + cb * 8);
            cp_async16(sb + AV_L + e * 144 + cb * 16,
                       vbl + (size_t)e * 1024 + kt * 64 + cb * 8);
        }
        asm volatile("cp.async.commit_group;" ::: "memory");
        asm volatile("cp.async.wait_group 0;" ::: "memory");
        __syncthreads();

        // ---- S = Q K^T (3-term split) ----
        #pragma unroll
        for (int j = 0; j < 8; j++)
            #pragma unroll
            for (int q = 0; q < 4; q++) S[j][q] = 0.f;
        #pragma unroll
        for (int kb = 0; kb < 8; kb++) {
            uint32_t ah[4], al[4];
            uint32_t qAddr = sb + AQ_H + (wid * 16 + row_off) * 272 + kb * 32 + half16;
            LDSM_X4(ah[0], ah[1], ah[2], ah[3], qAddr);
            LDSM_X4(al[0], al[1], al[2], al[3], qAddr + (AQ_L - AQ_H));
            #pragma unroll
            for (int np = 0; np < 4; np++) {
                uint32_t bh0[2], bh1[2], bl0[2], bl1[2];
                uint32_t kAddr = sb + AK_H + (np * 16 + row_off) * 272 + kb * 32 + half16;
                LDSM_X4(bh0[0], bh1[0], bh0[1], bh1[1], kAddr);
                LDSM_X4(bl0[0], bl1[0], bl0[1], bl1[1], kAddr + (AK_L - AK_H));
                mma_f16(S[2 * np],     ah, bh0);
                mma_f16(S[2 * np],     ah, bl0);
                mma_f16(S[2 * np],     al, bh0);
                mma_f16(S[2 * np + 1], ah, bh1);
                mma_f16(S[2 * np + 1], ah, bl1);
                mma_f16(S[2 * np + 1], al, bh1);
            }
        }

        // ---- online softmax ----
        float mx0 = -1e30f, mx1 = -1e30f;
        #pragma unroll
        for (int j = 0; j < 8; j++) {
            #pragma unroll
            for (int q = 0; q < 4; q++) {
                float sv = S[j][q] * scale;
                if (kt == qt) {
                    int col = j * 8 + t4 * 2 + (q & 1);
                    int row = wid * 16 + g + (q >> 1) * 8;
                    if (col > row) sv = -1e30f;
                }
                S[j][q] = sv;
                if (q < 2) mx0 = fmaxf(mx0, sv);
                else       mx1 = fmaxf(mx1, sv);
            }
        }
        mx0 = fmaxf(mx0, __shfl_xor_sync(0xffffffffu, mx0, 1));
        mx0 = fmaxf(mx0, __shfl_xor_sync(0xffffffffu, mx0, 2));
        mx1 = fmaxf(mx1, __shfl_xor_sync(0xffffffffu, mx1, 1));
        mx1 = fmaxf(mx1, __shfl_xor_sync(0xffffffffu, mx1, 2));
        float mn0 = fmaxf(m0, mx0), mn1 = fmaxf(m1, mx1);
        float alpha0 = __expf(m0 - mn0), alpha1 = __expf(m1 - mn1);
        float sum0 = 0.f, sum1 = 0.f;
        #pragma unroll
        for (int j = 0; j < 8; j++) {
            float p0 = __expf(S[j][0] - mn0);
            float p1 = __expf(S[j][1] - mn0);
            float p2 = __expf(S[j][2] - mn1);
            float p3 = __expf(S[j][3] - mn1);
            S[j][0] = p0; S[j][1] = p1; S[j][2] = p2; S[j][3] = p3;
            sum0 += p0 + p1; sum1 += p2 + p3;
        }
        sum0 += __shfl_xor_sync(0xffffffffu, sum0, 1);
        sum0 += __shfl_xor_sync(0xffffffffu, sum0, 2);
        sum1 += __shfl_xor_sync(0xffffffffu, sum1, 1);
        sum1 += __shfl_xor_sync(0xffffffffu, sum1, 2);
        l0 = l0 * alpha0 + sum0;
        l1 = l1 * alpha1 + sum1;
        m0 = mn0; m1 = mn1;
        #pragma unroll
        for (int nb = 0; nb < 16; nb++) {
            Oa[nb][0] *= alpha0; Oa[nb][1] *= alpha0;
            Oa[nb][2] *= alpha1; Oa[nb][3] *= alpha1;
        }

        // ---- O += P V (3-term split) ----
        #pragma unroll
        for (int kb = 0; kb < 4; kb++) {
            int j0 = 2 * kb, j1 = 2 * kb + 1;
            uint32_t pah[4], pal[4];
            {
                __half h0, h1, lo0, lo1;
                f16split(S[j0][0], h0, lo0); f16split(S[j0][1], h1, lo1);
                pah[0] = pack_h2(h0, h1);  pal[0] = pack_h2(lo0, lo1);
                f16split(S[j0][2], h0, lo0); f16split(S[j0][3], h1, lo1);
                pah[1] = pack_h2(h0, h1);  pal[1] = pack_h2(lo0, lo1);
                f16split(S[j1][0], h0, lo0); f16split(S[j1][1], h1, lo1);
                pah[2] = pack_h2(h0, h1);  pal[2] = pack_h2(lo0, lo1);
                f16split(S[j1][2], h0, lo0); f16split(S[j1][3], h1, lo1);
                pah[3] = pack_h2(h0, h1);  pal[3] = pack_h2(lo0, lo1);
            }
            #pragma unroll
            for (int ep = 0; ep < 8; ep++) {
                uint32_t vh0[2], vh1[2], vl0[2], vl1[2];
                uint32_t vAddr = sb + AV_H + (ep * 16 + row_off) * 144 + kb * 32 + half16;
                LDSM_X4(vh0[0], vh1[0], vh0[1], vh1[1], vAddr);
                LDSM_X4(vl0[0], vl1[0], vl0[1], vl1[1], vAddr + (AV_L - AV_H));
                mma_f16(Oa[2 * ep],     pah, vh0);
                mma_f16(Oa[2 * ep],     pah, vl0);
                mma_f16(Oa[2 * ep],     pal, vh0);
                mma_f16(Oa[2 * ep + 1], pah, vh1);
                mma_f16(Oa[2 * ep + 1], pah, vl1);
                mma_f16(Oa[2 * ep + 1], pal, vh1);
            }
        }
        __syncthreads();
    }

    // ---- epilogue: O /= l, write fp32 ----
    float inv0 = 1.f / l0, inv1 = 1.f / l1;
    int b = bh / HH, h = bh % HH;
    int trow = qt * 64 + wid * 16 + g;
    float* o0 = att + ((size_t)(b * TT + trow)) * DD + h * HSZ;
    float* o1 = att + ((size_t)(b * TT + trow + 8)) * DD + h * HSZ;
    #pragma unroll
    for (int nb = 0; nb < 16; nb++) {
        int e = nb * 8 + t4 * 2;
        *(float2*)(o0 + e) = make_float2(Oa[nb][0] * inv0, Oa[nb][1] * inv0);
        *(float2*)(o1 + e) = make_float2(Oa[nb][2] * inv1, Oa[nb][3] * inv1);
    }
}

// ======================= host orchestration =======================
extern "C" void kernel_launch(void* const* d_in, const int* in_sizes, int n_in,
                              void* d_out, int out_size) {
    const int*   idx     = (const int*)d_in[0];
    const float* tok_emb = (const float*)d_in[1];
    const float* pos_emb = (const float*)d_in[2];
    const float* wq      = (const float*)d_in[3];
    const float* wk      = (const float*)d_in[4];
    const float* wv      = (const float*)d_in[5];
    const float* wo      = (const float*)d_in[6];
    const float* bo      = (const float*)d_in[7];
    const float* w1      = (const float*)d_in[8];
    const float* b1      = (const float*)d_in[9];
    const float* w2      = (const float*)d_in[10];
    const float* b2      = (const float*)d_in[11];
    const float* g1      = (const float*)d_in[12];
    const float* be1     = (const float*)d_in[13];
    const float* g2      = (const float*)d_in[14];
    const float* be2     = (const float*)d_in[15];
    const float* wlm     = (const float*)d_in[16];
    const float* blm     = (const float*)d_in[17];
    float* out = (float*)d_out;

    float *px, *ph, *patt, *pff;
    __half *pqkvh, *pqkvl;
    __half *pqkvT_h, *pqkvT_l, *pwoT_h, *pwoT_l, *pw1T_h, *pw1T_l,
           *pw2T_h, *pw2T_l, *plmT_h, *plmT_l;
    cudaGetSymbolAddress((void**)&px,   g_x);
    cudaGetSymbolAddress((void**)&ph,   g_h);
    cudaGetSymbolAddress((void**)&patt, g_att);
    cudaGetSymbolAddress((void**)&pff,  g_ff);
    cudaGetSymbolAddress((void**)&pqkvh, g_qkvh);
    cudaGetSymbolAddress((void**)&pqkvl, g_qkvl);
    cudaGetSymbolAddress((void**)&pqkvT_h, g_wqkvT_hi);
    cudaGetSymbolAddress((void**)&pqkvT_l, g_wqkvT_lo);
    cudaGetSymbolAddress((void**)&pwoT_h,  g_woT_hi);
    cudaGetSymbolAddress((void**)&pwoT_l,  g_woT_lo);
    cudaGetSymbolAddress((void**)&pw1T_h,  g_w1T_hi);
    cudaGetSymbolAddress((void**)&pw1T_l,  g_w1T_lo);
    cudaGetSymbolAddress((void**)&pw2T_h,  g_w2T_hi);
    cudaGetSymbolAddress((void**)&pw2T_l,  g_w2T_lo);
    cudaGetSymbolAddress((void**)&plmT_h,  g_wlmT_hi);
    cudaGetSymbolAddress((void**)&plmT_l,  g_wlmT_lo);

    cudaFuncSetAttribute(mma_gemm_k<1>, cudaFuncAttributeMaxDynamicSharedMemorySize, GEMM_SMEM_BYTES);
    cudaFuncSetAttribute(mma_gemm_k<2>, cudaFuncAttributeMaxDynamicSharedMemorySize, GEMM_SMEM_BYTES);
    cudaFuncSetAttribute(mma_gemm_k<3>, cudaFuncAttributeMaxDynamicSharedMemorySize, GEMM_SMEM_BYTES);
    cudaFuncSetAttribute(mma_gemm_k<4>, cudaFuncAttributeMaxDynamicSharedMemorySize, GEMM_SMEM_BYTES);
    cudaFuncSetAttribute(flash_attn_k, cudaFuncAttributeMaxDynamicSharedMemorySize, ATT_SMEM);

    // weight prep (transpose + fp16 split) + embedding
    {
        int total = LL * 3 * DD * DD;
        prep_qkvT_k<<<(total + 255) / 256, 256>>>(wq, wk, wv);
        dim3 blk(32, 8);
        tsplit_k<<<dim3(DD / 32, DD / 32, LL), blk>>>(wo, pwoT_h, pwoT_l, DD, DD);
        tsplit_k<<<dim3(FFD / 32, DD / 32, LL), blk>>>(w1, pw1T_h, pw1T_l, DD, FFD);
        tsplit_k<<<dim3(DD / 32, FFD / 32, LL), blk>>>(w2, pw2T_h, pw2T_l, FFD, DD);
        tsplit_k<<<dim3(VV / 32, DD / 32, 1), blk>>>(wlm, plmT_h, plmT_l, DD, VV);
        embed_k<<<(MM * DD + 255) / 256, 256>>>(idx, tok_emb, pos_emb);
    }

    for (int l = 0; l < LL; l++) {
        layernorm_k<<<MM, 256>>>(px, g1 + l * DD, be1 + l * DD, ph);
        // qkv: [M, 2304] -> split fp16 q/k/v buffers
        mma_gemm_k<4><<<dim3(3 * DD / 128, MM / 128), 256, GEMM_SMEM_BYTES>>>(
            MM, 3 * DD, DD, ph,
            pqkvT_h + (size_t)l * 3 * DD * DD,
            pqkvT_l + (size_t)l * 3 * DD * DD,
            nullptr, nullptr, nullptr, pqkvh, pqkvl);
        // fused flash attention
        flash_attn_k<<<dim3(16, 24), 128, ATT_SMEM>>>(pqkvh, pqkvl, patt);
        // proj + bias + residual
        mma_gemm_k<3><<<dim3(DD / 128, MM / 128), 256, GEMM_SMEM_BYTES>>>(
            MM, DD, DD, patt,
            pwoT_h + (size_t)l * DD * DD,
            pwoT_l + (size_t)l * DD * DD,
            bo + l * DD, px, px, nullptr, nullptr);
        layernorm_k<<<MM, 256>>>(px, g2 + l * DD, be2 + l * DD, ph);
        // ff1: bias + relu
        mma_gemm_k<2><<<dim3(FFD / 128, MM / 128), 256, GEMM_SMEM_BYTES>>>(
            MM, FFD, DD, ph,
            pw1T_h + (size_t)l * FFD * DD,
            pw1T_l + (size_t)l * FFD * DD,
            b1 + l * FFD, nullptr, pff, nullptr, nullptr);
        // ff2: bias + residual
        mma_gemm_k<3><<<dim3(DD / 128, MM / 128), 256, GEMM_SMEM_BYTES>>>(
            MM, DD, FFD, pff,
            pw2T_h + (size_t)l * DD * FFD,
            pw2T_l + (size_t)l * DD * FFD,
            b2 + l * DD, px, px, nullptr, nullptr);
    }

    // LM head: out = x @ wlm + blm
    mma_gemm_k<1><<<dim3(VV / 128, MM / 128), 256, GEMM_SMEM_BYTES>>>(
        MM, VV, DD, px, plmT_h, plmT_l, blm, nullptr, out, nullptr, nullptr);
}